// round 8
// baseline (speedup 1.0000x reference)
#include <cuda_runtime.h>
#include <cuda_bf16.h>
#include <cstdint>

#define NB      131072
#define D       256
#define LEAVES  4
#define MID     2

typedef unsigned long long u64;
union U64F2 { u64 u; float2 f; };

__device__ __forceinline__ uint32_t smem_u32(const void* p) {
    uint32_t a;
    asm("{ .reg .u64 t; cvta.to.shared.u64 t, %1; cvt.u32.u64 %0, t; }"
        : "=r"(a) : "l"(p));
    return a;
}

__device__ __forceinline__ uint32_t pack_bf2(__nv_bfloat16 a, __nv_bfloat16 b) {
    __nv_bfloat162 p = __halves2bfloat162(a, b);
    return *reinterpret_cast<uint32_t*>(&p);
}

__device__ __forceinline__
void mma_bf16(float* c, const uint32_t a[4], uint32_t b0, uint32_t b1)
{
    asm("mma.sync.aligned.m16n8k16.row.col.f32.bf16.bf16.f32 "
        "{%0,%1,%2,%3}, {%4,%5,%6,%7}, {%8,%9}, {%0,%1,%2,%3};"
        : "+f"(c[0]), "+f"(c[1]), "+f"(c[2]), "+f"(c[3])
        : "r"(a[0]), "r"(a[1]), "r"(a[2]), "r"(a[3]), "r"(b0), "r"(b1));
}

#define LDSM_X4(r0, r1, r2, r3, addr)                                        \
    asm volatile("ldmatrix.sync.aligned.m8n8.x4.shared.b16 {%0,%1,%2,%3}, [%4];" \
        : "=r"(r0), "=r"(r1), "=r"(r2), "=r"(r3) : "r"(addr))

#define CP_ASYNC16(dst, src) \
    asm volatile("cp.async.cg.shared.global [%0], [%1], 16;" \
                 :: "r"(dst), "l"(src) : "memory")
#define CP_COMMIT()  asm volatile("cp.async.commit_group;" ::: "memory")
#define CP_WAIT1()   asm volatile("cp.async.wait_group 1;" ::: "memory")
#define CP_WAIT0()   asm volatile("cp.async.wait_group 0;" ::: "memory")

// ======================= global scratch =======================
__device__ int g_idx[NB];
__device__ int g_perm[NB];
__device__ int g_hist[LEAVES];
__device__ int g_base[LEAVES];
// 7 mats x [hi|lo plane] x [n=256][k=256] bf16  (B col-major for mma.sync)
__device__ __align__(16) unsigned short g_wimg[7 * 2 * 65536];

// ======================= gate / sort =======================
constexpr int GTILE = 64;
constexpr int GSTR  = D + 8;
constexpr int GOFF_SX  = 0;
constexpr int GOFF_WG  = GOFF_SX + GTILE * GSTR;
constexpr int GOFF_LOG = GOFF_WG + D * LEAVES;
constexpr int GOFF_H   = GOFF_LOG + GTILE * LEAVES;
constexpr int GATE_BYTES = (GOFF_H + LEAVES) * (int)sizeof(float);

__global__ void init_kernel() {
    if (threadIdx.x < LEAVES) g_hist[threadIdx.x] = 0;
}

__global__ void __launch_bounds__(256, 2)
gate_kernel(const float* __restrict__ x, const float* __restrict__ Wg,
            const float* __restrict__ bg)
{
    extern __shared__ float sm[];
    float* sX = sm + GOFF_SX;  float* sWg = sm + GOFF_WG;
    float* sLog = sm + GOFF_LOG;
    int* sH = reinterpret_cast<int*>(sm + GOFF_H);
    const int tid = threadIdx.x;
    const size_t row0 = (size_t)blockIdx.x * GTILE;

    const float4* xg = reinterpret_cast<const float4*>(x + row0 * D);
#pragma unroll
    for (int i = 0; i < (GTILE * D / 4) / 256; i++) {
        int li = tid + i * 256;
        int r = li / (D / 4), c4 = li % (D / 4);
        float4 v = xg[r * (D / 4) + c4];
        float* dst = &sX[r * GSTR + c4 * 4];
        dst[0] = v.x; dst[1] = v.y; dst[2] = v.z; dst[3] = v.w;
    }
    for (int i = tid; i < D * LEAVES; i += 256) sWg[i] = Wg[i];
    if (tid < LEAVES) sH[tid] = 0;
    __syncthreads();
    {
        int r = tid & (GTILE - 1);
        int e = tid >> 6;
        float acc = bg[e];
        const float* xr = &sX[r * GSTR];
#pragma unroll 8
        for (int d = 0; d < D; d++) acc = fmaf(xr[d], sWg[d * LEAVES + e], acc);
        sLog[r * LEAVES + e] = acc;
    }
    __syncthreads();
    if (tid < GTILE) {
        float best = sLog[tid * LEAVES];
        int bi = 0;
#pragma unroll
        for (int e = 1; e < LEAVES; e++) {
            float v = sLog[tid * LEAVES + e];
            if (v > best) { best = v; bi = e; }
        }
        g_idx[row0 + tid] = bi;
        atomicAdd(&sH[bi], 1);
    }
    __syncthreads();
    if (tid < LEAVES) atomicAdd(&g_hist[tid], sH[tid]);
}

__global__ void scan_kernel() {
    int b = 0;
    for (int e = 0; e < LEAVES; e++) { g_base[e] = b; b += g_hist[e]; }
}

__global__ void scatter_kernel() {
    __shared__ int cnt[LEAVES];
    __shared__ int boff[LEAVES];
    const int tid = threadIdx.x;
    const int r = blockIdx.x * blockDim.x + tid;
    if (tid < LEAVES) cnt[tid] = 0;
    __syncthreads();
    int e = g_idx[r];
    int my = atomicAdd(&cnt[e], 1);
    __syncthreads();
    if (tid < LEAVES) boff[tid] = atomicAdd(&g_base[tid], cnt[tid]);
    __syncthreads();
    g_perm[boff[e] + my] = r;
}

// ======== weight prep: fp32 W[k][n] -> bf16 hi/lo images img[n][k] ========
__global__ void prep_w_kernel(const float* __restrict__ Wl,
                              const float* __restrict__ Wm,
                              const float* __restrict__ Wr)
{
    int gid = blockIdx.x * 256 + threadIdx.x;      // 7*65536 total
    int mat = gid >> 16;
    int rem = gid & 0xFFFF;
    int n = rem >> 8, k = rem & 255;
    float v;
    if (mat < 4)      v = Wl[mat * 65536 + k * 256 + n];
    else if (mat < 6) v = Wm[(mat - 4) * 65536 + k * 256 + n];
    else              v = Wr[k * 256 + n];
    __nv_bfloat16 h = __float2bfloat16(v);
    float lof = v - __bfloat162float(h);
    __nv_bfloat16 l = __float2bfloat16(lof);
    unsigned short* base = g_wimg + (size_t)mat * 131072;
    base[n * 256 + k]         = __bfloat16_as_ushort(h);
    base[65536 + n * 256 + k] = __bfloat16_as_ushort(l);
}

// ======================= main mma.sync kernel (v2) =======================
constexpr int A_STR_B   = 264 * 2;                 // 528
constexpr int OFF_AHI   = 0;
constexpr int OFF_ALO   = 67584;
constexpr int OFF_B     = 135168;
constexpr int B_PLANE_B = 256 * 40 * 2;            // 20480
constexpr int B_BUF_B   = 2 * B_PLANE_B;           // 40960
constexpr int OFF_BIAS  = OFF_B + 2 * B_BUF_B;     // 217088
constexpr int OFF_ORIG  = OFF_BIAS + 768 * 4;      // 220160
constexpr int MMA_SMEM  = OFF_ORIG + 512;          // 220672

__global__ void __launch_bounds__(256, 1)
tree_mma_kernel(const float* __restrict__ x,
                const float* __restrict__ b_leaf,
                const float* __restrict__ b_mid,
                const float* __restrict__ b_root,
                float* __restrict__ out)
{
    extern __shared__ char smc[];
    int* sOrig = reinterpret_cast<int*>(smc + OFF_ORIG);
    float* sBias = reinterpret_cast<float*>(smc + OFF_BIAS);
    const uint32_t sbU = smem_u32(smc);

    const int tid = threadIdx.x;
    const int lane = tid & 31, w = tid >> 5;       // 8 warps
    const int wm = w & 1, wn = w >> 1;             // 2 x 4 warp grid, tile 64x64
    const int g = lane >> 2, tg = lane & 3;
    const size_t row0 = (size_t)blockIdx.x * 128;

    if (tid < 128) sOrig[tid] = g_perm[row0 + tid];
    __syncthreads();
    const int eL = g_idx[sOrig[0]];
    if (eL != g_idx[sOrig[127]]) return;          // mixed tile -> fallback
    const int eM = eL >> 1;
    const int matIdx[3] = { eL, 4 + eM, 6 };

    // ---- cp.async staging of B chunks (k32): 2 planes x 256 n x 5 x 16B ----
    auto stageB = [&](int gc, int buf) {
        const unsigned short* mbase = g_wimg + (size_t)matIdx[gc >> 3] * 131072
                                      + (gc & 7) * 32;        // kc*32 in u16
        const uint32_t dbase = sbU + OFF_B + buf * B_BUF_B + tid * 80;
#pragma unroll
        for (int p = 0; p < 2; p++) {
            const unsigned short* src = mbase + p * 65536 + tid * 256;
            const uint32_t dst = dbase + p * B_PLANE_B;
#pragma unroll
            for (int seg = 0; seg < 5; seg++)
                CP_ASYNC16(dst + seg * 16, src + seg * 8);
        }
    };

    // prologue: stage chunks 0 and 1
    stageB(0, 0);  CP_COMMIT();
    stageB(1, 1);  CP_COMMIT();

    for (int i = tid; i < 256; i += 256) {
        sBias[i]       = b_leaf[eL * 256 + i];
        sBias[256 + i] = b_mid[eM * 256 + i];
        sBias[512 + i] = b_root[i];
    }

    // ---- A init: thread -> (row tid>>1, 128-col half tid&1), split hi/lo ----
    {
        int r = tid >> 1, seg = tid & 1;
        const float4* xr = reinterpret_cast<const float4*>(
                               x + (size_t)sOrig[r] * D) + seg * 32;
        char* aH = smc + OFF_AHI + r * A_STR_B + seg * 256;
        char* aL = smc + OFF_ALO + r * A_STR_B + seg * 256;
#pragma unroll
        for (int i = 0; i < 32; i++) {
            float4 f = xr[i];
            __nv_bfloat16 h0 = __float2bfloat16(f.x), h1 = __float2bfloat16(f.y);
            __nv_bfloat16 h2 = __float2bfloat16(f.z), h3 = __float2bfloat16(f.w);
            uint2 hv, lv;
            hv.x = pack_bf2(h0, h1);
            hv.y = pack_bf2(h2, h3);
            lv.x = pack_bf2(__float2bfloat16(f.x - __bfloat162float(h0)),
                            __float2bfloat16(f.y - __bfloat162float(h1)));
            lv.y = pack_bf2(__float2bfloat16(f.z - __bfloat162float(h2)),
                            __float2bfloat16(f.w - __bfloat162float(h3)));
            *reinterpret_cast<uint2*>(aH + i * 8) = hv;
            *reinterpret_cast<uint2*>(aL + i * 8) = lv;
        }
    }

    // ldmatrix base addresses
    uint32_t aBaseH[4];
#pragma unroll
    for (int mt = 0; mt < 4; mt++)
        aBaseH[mt] = sbU + OFF_AHI
                   + (wm * 64 + mt * 16 + (lane & 15)) * A_STR_B
                   + (lane >> 4) * 16;
    const uint32_t bBase = sbU + OFF_B
        + (wn * 64 + (lane & 7) + ((lane >> 4) << 3)) * 80
        + (((lane >> 3) & 1) << 4);

    float acc[4][8][4];
#pragma unroll
    for (int mt = 0; mt < 4; mt++)
#pragma unroll
        for (int nt = 0; nt < 8; nt++)
#pragma unroll
            for (int q = 0; q < 4; q++) acc[mt][nt][q] = 0.f;

    __syncthreads();   // A planes + biases visible

#pragma unroll 1
    for (int gc = 0; gc < 24; gc++) {
        const int cur = gc & 1;
        // ensure staging of chunk gc is complete, visible to all warps
        if (gc < 23) CP_WAIT1(); else CP_WAIT0();
        __syncthreads();

        // ---- compute chunk gc (k32 = 2 k16-steps) ----
#pragma unroll
        for (int kk = 0; kk < 2; kk++) {
            const uint32_t koffA = (gc & 7) * 64 + kk * 32;
            uint32_t aH[4][4], aL[4][4];
#pragma unroll
            for (int mt = 0; mt < 4; mt++) {
                LDSM_X4(aH[mt][0], aH[mt][1], aH[mt][2], aH[mt][3],
                        aBaseH[mt] + koffA);
                LDSM_X4(aL[mt][0], aL[mt][1], aL[mt][2], aL[mt][3],
                        aBaseH[mt] + OFF_ALO + koffA);
            }
            const uint32_t bk = bBase + cur * B_BUF_B + kk * 32;
#pragma unroll
            for (int op = 0; op < 4; op++) {
                uint32_t bh0, bh1, bh2, bh3, bl0, bl1, bl2, bl3;
                LDSM_X4(bh0, bh1, bh2, bh3, bk + op * (16 * 80));
                LDSM_X4(bl0, bl1, bl2, bl3, bk + op * (16 * 80) + B_PLANE_B);
#pragma unroll
                for (int mt = 0; mt < 4; mt++) {
                    mma_bf16(acc[mt][2 * op],     aH[mt], bh0, bh1);
                    mma_bf16(acc[mt][2 * op],     aL[mt], bh0, bh1);
                    mma_bf16(acc[mt][2 * op],     aH[mt], bl0, bl1);
                    mma_bf16(acc[mt][2 * op + 1], aH[mt], bh2, bh3);
                    mma_bf16(acc[mt][2 * op + 1], aL[mt], bh2, bh3);
                    mma_bf16(acc[mt][2 * op + 1], aH[mt], bl2, bl3);
                }
            }
        }
        __syncthreads();   // all warps done reading buf `cur` (and A for epilogue)

        if (gc + 2 < 24) { stageB(gc + 2, cur); CP_COMMIT(); }

        // ---- layer epilogue ----
        if ((gc & 7) == 7) {
            const int l = gc >> 3;
            const float* sB = sBias + l * 256;
            if (l < 2) {
#pragma unroll
                for (int mt = 0; mt < 4; mt++) {
#pragma unroll
                    for (int nt = 0; nt < 8; nt++) {
                        int col = wn * 64 + nt * 8 + tg * 2;
                        float b0 = sB[col], b1 = sB[col + 1];
                        int rlo = wm * 64 + mt * 16 + g;
#pragma unroll
                        for (int half = 0; half < 2; half++) {
                            int r = rlo + half * 8;
                            float v0 = fmaxf(acc[mt][nt][2 * half]     + b0, 0.f);
                            float v1 = fmaxf(acc[mt][nt][2 * half + 1] + b1, 0.f);
                            __nv_bfloat16 h0 = __float2bfloat16(v0);
                            __nv_bfloat16 h1 = __float2bfloat16(v1);
                            uint32_t hv = pack_bf2(h0, h1);
                            uint32_t lv = pack_bf2(
                                __float2bfloat16(v0 - __bfloat162float(h0)),
                                __float2bfloat16(v1 - __bfloat162float(h1)));
                            char* pa = smc + OFF_AHI + r * A_STR_B + col * 2;
                            *reinterpret_cast<uint32_t*>(pa) = hv;
                            *reinterpret_cast<uint32_t*>(pa + OFF_ALO) = lv;
                            acc[mt][nt][2 * half] = 0.f;
                            acc[mt][nt][2 * half + 1] = 0.f;
                        }
                    }
                }
                __syncthreads();   // A rewrite visible before next layer
            } else {
#pragma unroll
                for (int mt = 0; mt < 4; mt++) {
#pragma unroll
                    for (int half = 0; half < 2; half++) {
                        int r = wm * 64 + mt * 16 + g + half * 8;
                        float* orow = out + (size_t)sOrig[r] * D;
#pragma unroll
                        for (int nt = 0; nt < 8; nt++) {
                            int col = wn * 64 + nt * 8 + tg * 2;
                            float2 v;
                            v.x = fmaxf(acc[mt][nt][2 * half]     + sB[col],     0.f);
                            v.y = fmaxf(acc[mt][nt][2 * half + 1] + sB[col + 1], 0.f);
                            *reinterpret_cast<float2*>(orow + col) = v;
                        }
                    }
                }
            }
        }
    }
}

// ======================= FFMA2 fallback for mixed 128-tiles =======================
constexpr int FTILE = 64;
constexpr int FKC = 16;
constexpr int FSTR = D + 8;
constexpr int FOFF_SX = 0;
constexpr int FOFF_SW = FOFF_SX + FTILE * FSTR;
constexpr int FOFF_BLEAF = FOFF_SW + FKC * D;
constexpr int FOFF_BMID = FOFF_BLEAF + LEAVES * D;
constexpr int FOFF_BROOT = FOFF_BMID + MID * D;
constexpr int FOFF_ORIG = FOFF_BROOT + D;
constexpr int FOFF_E = FOFF_ORIG + FTILE;
constexpr int FOFF_MM = FOFF_E + FTILE;
constexpr int FB_BYTES = (FOFF_MM + 2) * (int)sizeof(float);

#define FMA_F32X2(d, a, b, c) \
    asm("fma.rn.f32x2 %0, %1, %2, %3;" : "=l"(d) : "l"(a), "l"(b), "l"(c))
#define PACK2(d, xx) \
    asm("mov.b64 %0, {%1, %1};" : "=l"(d) : "r"(xx))

template <bool MASKED>
__device__ __forceinline__
void fb_gemm(const float* __restrict__ Wglob, float* sW, const float* sX,
             const float m[8], u64 (&acc2)[8][4], int tid, int r0, int c0)
{
#pragma unroll 1
    for (int kc = 0; kc < D; kc += FKC) {
        __syncthreads();
        const float4* wg4 = reinterpret_cast<const float4*>(Wglob + (size_t)kc * D);
        float4* sW4 = reinterpret_cast<float4*>(sW);
#pragma unroll
        for (int i = 0; i < (FKC * D / 4) / 256; i++)
            sW4[tid + i * 256] = wg4[tid + i * 256];
        __syncthreads();
#pragma unroll
        for (int k4 = 0; k4 < FKC; k4 += 4) {
            float4 a4[8];
#pragma unroll
            for (int i = 0; i < 8; i++) {
                a4[i] = *reinterpret_cast<const float4*>(&sX[(r0 + i) * FSTR + kc + k4]);
                if (MASKED) {
                    a4[i].x *= m[i]; a4[i].y *= m[i];
                    a4[i].z *= m[i]; a4[i].w *= m[i];
                }
            }
#pragma unroll
            for (int kk = 0; kk < 4; kk++) {
                const ulonglong2* bp =
                    reinterpret_cast<const ulonglong2*>(&sW[(k4 + kk) * D + c0]);
                ulonglong2 b01 = bp[0];
                ulonglong2 b23 = bp[1];
#pragma unroll
                for (int i = 0; i < 8; i++) {
                    float av = (kk == 0) ? a4[i].x : (kk == 1) ? a4[i].y
                             : (kk == 2) ? a4[i].z : a4[i].w;
                    u64 a2;
                    PACK2(a2, __float_as_uint(av));
                    FMA_F32X2(acc2[i][0], a2, b01.x, acc2[i][0]);
                    FMA_F32X2(acc2[i][1], a2, b01.y, acc2[i][1]);
                    FMA_F32X2(acc2[i][2], a2, b23.x, acc2[i][2]);
                    FMA_F32X2(acc2[i][3], a2, b23.y, acc2[i][3]);
                }
            }
        }
    }
}

__global__ void __launch_bounds__(256, 2)
fallback_kernel(const float* __restrict__ x,
                const float* __restrict__ W_leaf, const float* __restrict__ b_leaf,
                const float* __restrict__ W_mid,  const float* __restrict__ b_mid,
                const float* __restrict__ W_root, const float* __restrict__ b_root,
                float* __restrict__ out)
{
    const size_t t128 = (size_t)(blockIdx.x >> 1) * 128;
    if (g_idx[g_perm[t128]] == g_idx[g_perm[t128 + 127]]) return;

    extern __shared__ float sm[];
    float* sX = sm + FOFF_SX;  float* sW = sm + FOFF_SW;
    float* sBlf = sm + FOFF_BLEAF;  float* sBmd = sm + FOFF_BMID;
    float* sBrt = sm + FOFF_BROOT;
    int* sOrig = reinterpret_cast<int*>(sm + FOFF_ORIG);
    int* sE = reinterpret_cast<int*>(sm + FOFF_E);
    int* sMM = reinterpret_cast<int*>(sm + FOFF_MM);

    const int tid = threadIdx.x;
    const size_t row0 = (size_t)blockIdx.x * FTILE;
    const int tx = tid & 31, ty = tid >> 5;
    const int r0 = ty * 8, c0 = tx * 8;

    if (tid < FTILE) {
        int orig = g_perm[row0 + tid];
        sOrig[tid] = orig;
        sE[tid] = g_idx[orig];
    }
    if (tid == FTILE) { sMM[0] = LEAVES; sMM[1] = -1; }
    __syncthreads();

#pragma unroll
    for (int i = 0; i < (FTILE * D / 4) / 256; i++) {
        int li = tid + i * 256;
        int r = li / (D / 4), c4 = li % (D / 4);
        const float4* src = reinterpret_cast<const float4*>(x + (size_t)sOrig[r] * D);
        float4 v = src[c4];
        float* dst = &sX[r * FSTR + c4 * 4];
        dst[0] = v.x; dst[1] = v.y; dst[2] = v.z; dst[3] = v.w;
    }
    for (int i = tid; i < LEAVES * D; i += 256) sBlf[i] = b_leaf[i];
    for (int i = tid; i < MID * D;    i += 256) sBmd[i] = b_mid[i];
    for (int i = tid; i < D;          i += 256) sBrt[i] = b_root[i];
    if (tid < FTILE) {
        atomicMin(&sMM[0], sE[tid]);
        atomicMax(&sMM[1], sE[tid]);
    }
    __syncthreads();

    const int emin = sMM[0], emax = sMM[1];
    u64 acc2[8][4];
#pragma unroll
    for (int i = 0; i < 8; i++)
#pragma unroll
        for (int j = 0; j < 4; j++) acc2[i][j] = 0ull;
    float m[8];

    if (emin == emax) {
        fb_gemm<false>(W_leaf + (size_t)emin * D * D, sW, sX, m, acc2, tid, r0, c0);
    } else {
        for (int e = emin; e <= emax; e++) {
#pragma unroll
            for (int i = 0; i < 8; i++) m[i] = (sE[r0 + i] == e) ? 1.f : 0.f;
            fb_gemm<true>(W_leaf + (size_t)e * D * D, sW, sX, m, acc2, tid, r0, c0);
        }
    }
#pragma unroll
    for (int i = 0; i < 8; i++) {
        int e = sE[r0 + i];
#pragma unroll
        for (int p = 0; p < 4; p++) {
            U64F2 u; u.u = acc2[i][p];
            sX[(r0 + i) * FSTR + c0 + 2 * p]     = fmaxf(u.f.x + sBlf[e * D + c0 + 2 * p], 0.f);
            sX[(r0 + i) * FSTR + c0 + 2 * p + 1] = fmaxf(u.f.y + sBlf[e * D + c0 + 2 * p + 1], 0.f);
            acc2[i][p] = 0ull;
        }
    }

    const int pmin = emin >> 1, pmax = emax >> 1;
    if (pmin == pmax) {
        fb_gemm<false>(W_mid + (size_t)pmin * D * D, sW, sX, m, acc2, tid, r0, c0);
    } else {
        for (int p = pmin; p <= pmax; p++) {
#pragma unroll
            for (int i = 0; i < 8; i++) m[i] = ((sE[r0 + i] >> 1) == p) ? 1.f : 0.f;
            fb_gemm<true>(W_mid + (size_t)p * D * D, sW, sX, m, acc2, tid, r0, c0);
        }
    }
#pragma unroll
    for (int i = 0; i < 8; i++) {
        int pp = sE[r0 + i] >> 1;
#pragma unroll
        for (int p = 0; p < 4; p++) {
            U64F2 u; u.u = acc2[i][p];
            sX[(r0 + i) * FSTR + c0 + 2 * p]     = fmaxf(u.f.x + sBmd[pp * D + c0 + 2 * p], 0.f);
            sX[(r0 + i) * FSTR + c0 + 2 * p + 1] = fmaxf(u.f.y + sBmd[pp * D + c0 + 2 * p + 1], 0.f);
            acc2[i][p] = 0ull;
        }
    }

    fb_gemm<false>(W_root, sW, sX, m, acc2, tid, r0, c0);
#pragma unroll
    for (int i = 0; i < 8; i++) {
        float v[8];
#pragma unroll
        for (int p = 0; p < 4; p++) {
            U64F2 u; u.u = acc2[i][p];
            v[2 * p]     = fmaxf(u.f.x + sBrt[c0 + 2 * p],     0.f);
            v[2 * p + 1] = fmaxf(u.f.y + sBrt[c0 + 2 * p + 1], 0.f);
        }
        float4* o = reinterpret_cast<float4*>(out + (size_t)sOrig[r0 + i] * D + c0);
        o[0] = make_float4(v[0], v[1], v[2], v[3]);
        o[1] = make_float4(v[4], v[5], v[6], v[7]);
    }
}

// ======================= launch =======================
extern "C" void kernel_launch(void* const* d_in, const int* in_sizes, int n_in,
                              void* d_out, int out_size)
{
    const float* x      = (const float*)d_in[0];
    const float* Wg     = (const float*)d_in[1];
    const float* bg     = (const float*)d_in[2];
    const float* W_leaf = (const float*)d_in[3];
    const float* b_leaf = (const float*)d_in[4];
    const float* W_mid  = (const float*)d_in[5];
    const float* b_mid  = (const float*)d_in[6];
    const float* W_root = (const float*)d_in[7];
    const float* b_root = (const float*)d_in[8];
    float* out = (float*)d_out;

    cudaFuncSetAttribute(gate_kernel,
                         cudaFuncAttributeMaxDynamicSharedMemorySize, GATE_BYTES);
    cudaFuncSetAttribute(tree_mma_kernel,
                         cudaFuncAttributeMaxDynamicSharedMemorySize, MMA_SMEM);
    cudaFuncSetAttribute(fallback_kernel,
                         cudaFuncAttributeMaxDynamicSharedMemorySize, FB_BYTES);

    init_kernel<<<1, 32>>>();
    prep_w_kernel<<<7 * 65536 / 256, 256>>>(W_leaf, W_mid, W_root);
    gate_kernel<<<NB / GTILE, 256, GATE_BYTES>>>(x, Wg, bg);
    scan_kernel<<<1, 1>>>();
    scatter_kernel<<<NB / 256, 256>>>();
    tree_mma_kernel<<<NB / 128, 256, MMA_SMEM>>>(x, b_leaf, b_mid, b_root, out);
    fallback_kernel<<<NB / FTILE, 256, FB_BYTES>>>(
        x, W_leaf, b_leaf, W_mid, b_mid, W_root, b_root, out);
}

// round 10
// speedup vs baseline: 1.0369x; 1.0369x over previous
#include <cuda_runtime.h>
#include <cuda_bf16.h>
#include <cstdint>

#define NB      131072
#define D       256
#define LEAVES  4
#define MID     2

typedef unsigned long long u64;
union U64F2 { u64 u; float2 f; };

__device__ __forceinline__ uint32_t smem_u32(const void* p) {
    uint32_t a;
    asm("{ .reg .u64 t; cvta.to.shared.u64 t, %1; cvt.u32.u64 %0, t; }"
        : "=r"(a) : "l"(p));
    return a;
}

__device__ __forceinline__ uint32_t pack_bf2(__nv_bfloat16 a, __nv_bfloat16 b) {
    __nv_bfloat162 p = __halves2bfloat162(a, b);
    return *reinterpret_cast<uint32_t*>(&p);
}

__device__ __forceinline__
void mma_bf16(float* c, const uint32_t a[4], uint32_t b0, uint32_t b1)
{
    asm("mma.sync.aligned.m16n8k16.row.col.f32.bf16.bf16.f32 "
        "{%0,%1,%2,%3}, {%4,%5,%6,%7}, {%8,%9}, {%0,%1,%2,%3};"
        : "+f"(c[0]), "+f"(c[1]), "+f"(c[2]), "+f"(c[3])
        : "r"(a[0]), "r"(a[1]), "r"(a[2]), "r"(a[3]), "r"(b0), "r"(b1));
}

#define LDSM_X4(r0, r1, r2, r3, addr)                                        \
    asm volatile("ldmatrix.sync.aligned.m8n8.x4.shared.b16 {%0,%1,%2,%3}, [%4];" \
        : "=r"(r0), "=r"(r1), "=r"(r2), "=r"(r3) : "r"(addr))

#define CP_ASYNC16(dst, src) \
    asm volatile("cp.async.cg.shared.global [%0], [%1], 16;" \
                 :: "r"(dst), "l"(src) : "memory")
#define CP_COMMIT()  asm volatile("cp.async.commit_group;" ::: "memory")
#define CP_WAIT1()   asm volatile("cp.async.wait_group 1;" ::: "memory")
#define CP_WAIT0()   asm volatile("cp.async.wait_group 0;" ::: "memory")

// ======================= global scratch =======================
__device__ int g_idx[NB];
__device__ int g_perm[NB];
__device__ int g_hist[LEAVES];
__device__ int g_base[LEAVES];
// 7 mats x [hi|lo plane] x [n=256][k=256] bf16  (B col-major for mma.sync)
__device__ __align__(16) unsigned short g_wimg[7 * 2 * 65536];

// ======================= gate / sort =======================
constexpr int GTILE = 64;
constexpr int GSTR  = D + 8;
constexpr int GOFF_SX  = 0;
constexpr int GOFF_WG  = GOFF_SX + GTILE * GSTR;
constexpr int GOFF_LOG = GOFF_WG + D * LEAVES;
constexpr int GOFF_H   = GOFF_LOG + GTILE * LEAVES;
constexpr int GATE_BYTES = (GOFF_H + LEAVES) * (int)sizeof(float);

__global__ void init_kernel() {
    if (threadIdx.x < LEAVES) g_hist[threadIdx.x] = 0;
}

__global__ void __launch_bounds__(256, 2)
gate_kernel(const float* __restrict__ x, const float* __restrict__ Wg,
            const float* __restrict__ bg)
{
    extern __shared__ float sm[];
    float* sX = sm + GOFF_SX;  float* sWg = sm + GOFF_WG;
    float* sLog = sm + GOFF_LOG;
    int* sH = reinterpret_cast<int*>(sm + GOFF_H);
    const int tid = threadIdx.x;
    const size_t row0 = (size_t)blockIdx.x * GTILE;

    const float4* xg = reinterpret_cast<const float4*>(x + row0 * D);
#pragma unroll
    for (int i = 0; i < (GTILE * D / 4) / 256; i++) {
        int li = tid + i * 256;
        int r = li / (D / 4), c4 = li % (D / 4);
        float4 v = xg[r * (D / 4) + c4];
        float* dst = &sX[r * GSTR + c4 * 4];
        dst[0] = v.x; dst[1] = v.y; dst[2] = v.z; dst[3] = v.w;
    }
    for (int i = tid; i < D * LEAVES; i += 256) sWg[i] = Wg[i];
    if (tid < LEAVES) sH[tid] = 0;
    __syncthreads();
    {
        int r = tid & (GTILE - 1);
        int e = tid >> 6;
        float acc = bg[e];
        const float* xr = &sX[r * GSTR];
#pragma unroll 8
        for (int d = 0; d < D; d++) acc = fmaf(xr[d], sWg[d * LEAVES + e], acc);
        sLog[r * LEAVES + e] = acc;
    }
    __syncthreads();
    if (tid < GTILE) {
        float best = sLog[tid * LEAVES];
        int bi = 0;
#pragma unroll
        for (int e = 1; e < LEAVES; e++) {
            float v = sLog[tid * LEAVES + e];
            if (v > best) { best = v; bi = e; }
        }
        g_idx[row0 + tid] = bi;
        atomicAdd(&sH[bi], 1);
    }
    __syncthreads();
    if (tid < LEAVES) atomicAdd(&g_hist[tid], sH[tid]);
}

__global__ void scan_kernel() {
    int b = 0;
    for (int e = 0; e < LEAVES; e++) { g_base[e] = b; b += g_hist[e]; }
}

__global__ void scatter_kernel() {
    __shared__ int cnt[LEAVES];
    __shared__ int boff[LEAVES];
    const int tid = threadIdx.x;
    const int r = blockIdx.x * blockDim.x + tid;
    if (tid < LEAVES) cnt[tid] = 0;
    __syncthreads();
    int e = g_idx[r];
    int my = atomicAdd(&cnt[e], 1);
    __syncthreads();
    if (tid < LEAVES) boff[tid] = atomicAdd(&g_base[tid], cnt[tid]);
    __syncthreads();
    g_perm[boff[e] + my] = r;
}

// ======== weight prep: fp32 W[k][n] -> bf16 hi/lo images img[n][k] ========
__global__ void prep_w_kernel(const float* __restrict__ Wl,
                              const float* __restrict__ Wm,
                              const float* __restrict__ Wr)
{
    int gid = blockIdx.x * 256 + threadIdx.x;      // 7*65536 total
    int mat = gid >> 16;
    int rem = gid & 0xFFFF;
    int n = rem >> 8, k = rem & 255;
    float v;
    if (mat < 4)      v = Wl[mat * 65536 + k * 256 + n];
    else if (mat < 6) v = Wm[(mat - 4) * 65536 + k * 256 + n];
    else              v = Wr[k * 256 + n];
    __nv_bfloat16 h = __float2bfloat16(v);
    float lof = v - __bfloat162float(h);
    __nv_bfloat16 l = __float2bfloat16(lof);
    unsigned short* base = g_wimg + (size_t)mat * 131072;
    base[n * 256 + k]         = __bfloat16_as_ushort(h);
    base[65536 + n * 256 + k] = __bfloat16_as_ushort(l);
}

// ================= main mma.sync kernel (v4: 3-buf cp.async, 48B stride) ===
constexpr int A_STR_B   = 264 * 2;                 // 528
constexpr int OFF_AHI   = 0;
constexpr int OFF_ALO   = 67584;
constexpr int OFF_B     = 135168;
constexpr int B_STRIDE  = 48;                      // 12 words: cp.async-16 legal,
                                                   // ldmatrix conflict-free
constexpr int B_PLANE_B = 256 * B_STRIDE;          // 12288 (k16 chunk plane)
constexpr int B_CHUNK_B = 2 * B_PLANE_B;           // 24576
constexpr int N_BUF     = 3;
constexpr int OFF_BIAS  = OFF_B + N_BUF * B_CHUNK_B;   // 208896
constexpr int OFF_ORIG  = OFF_BIAS + 768 * 4;          // 211968
constexpr int MMA_SMEM  = OFF_ORIG + 512;              // 212480

__global__ void __launch_bounds__(512, 1)
tree_mma_kernel(const float* __restrict__ x,
                const float* __restrict__ b_leaf,
                const float* __restrict__ b_mid,
                const float* __restrict__ b_root,
                float* __restrict__ out)
{
    extern __shared__ char smc[];
    int* sOrig = reinterpret_cast<int*>(smc + OFF_ORIG);
    float* sBias = reinterpret_cast<float*>(smc + OFF_BIAS);
    const uint32_t sbU = smem_u32(smc);

    const int tid = threadIdx.x;
    const int lane = tid & 31, w = tid >> 5;       // 16 warps
    const int wm = w & 3, wn = w >> 2;             // 4 x 4 grid, tile 32x64
    const int g = lane >> 2, tg = lane & 3;
    const size_t row0 = (size_t)blockIdx.x * 128;

    if (tid < 128) sOrig[tid] = g_perm[row0 + tid];
    __syncthreads();
    const int eL = g_idx[sOrig[0]];
    if (eL != g_idx[sOrig[127]]) return;          // mixed tile -> fallback
    const int eM = eL >> 1;
    const int matIdx[3] = { eL, 4 + eM, 6 };

    // ---- cp.async staging of a k16 chunk: 2 planes x 256 rows x 32B ----
    const int sp = tid >> 8, sn = tid & 255;       // (plane, n-row) per thread
    auto stageB = [&](int gc, int buf) {
        const unsigned short* src = g_wimg + (size_t)matIdx[gc >> 4] * 131072
                                    + sp * 65536 + sn * 256 + (gc & 15) * 16;
        const uint32_t dst = sbU + OFF_B + buf * B_CHUNK_B
                             + sp * B_PLANE_B + sn * B_STRIDE;   // 16B aligned
        CP_ASYNC16(dst, src);
        CP_ASYNC16(dst + 16, src + 8);
    };

    // prologue: stage chunks 0,1
    stageB(0, 0);  CP_COMMIT();
    stageB(1, 1);  CP_COMMIT();

    for (int i = tid; i < 256; i += 512) {
        sBias[i]       = b_leaf[eL * 256 + i];
        sBias[256 + i] = b_mid[eM * 256 + i];
        sBias[512 + i] = b_root[i];
    }

    // ---- A init: thread -> (row tid>>2, 64-col segment tid&3), split hi/lo ----
    {
        int r = tid >> 2, seg = tid & 3;
        const float4* xr = reinterpret_cast<const float4*>(
                               x + (size_t)sOrig[r] * D) + seg * 16;
        char* aH = smc + OFF_AHI + r * A_STR_B + seg * 128;
        char* aL = smc + OFF_ALO + r * A_STR_B + seg * 128;
#pragma unroll
        for (int i = 0; i < 16; i++) {
            float4 f = xr[i];
            __nv_bfloat16 h0 = __float2bfloat16(f.x), h1 = __float2bfloat16(f.y);
            __nv_bfloat16 h2 = __float2bfloat16(f.z), h3 = __float2bfloat16(f.w);
            uint2 hv, lv;
            hv.x = pack_bf2(h0, h1);
            hv.y = pack_bf2(h2, h3);
            lv.x = pack_bf2(__float2bfloat16(f.x - __bfloat162float(h0)),
                            __float2bfloat16(f.y - __bfloat162float(h1)));
            lv.y = pack_bf2(__float2bfloat16(f.z - __bfloat162float(h2)),
                            __float2bfloat16(f.w - __bfloat162float(h3)));
            *reinterpret_cast<uint2*>(aH + i * 8) = hv;
            *reinterpret_cast<uint2*>(aL + i * 8) = lv;
        }
    }

    // ldmatrix base addresses
    uint32_t aBaseH[2];
#pragma unroll
    for (int mt = 0; mt < 2; mt++)
        aBaseH[mt] = sbU + OFF_AHI
                   + (wm * 32 + mt * 16 + (lane & 15)) * A_STR_B
                   + (lane >> 4) * 16;
    const uint32_t bBase = sbU + OFF_B
        + (wn * 64 + (lane & 7) + ((lane >> 4) << 3)) * B_STRIDE
        + (((lane >> 3) & 1) << 4);

    float acc[2][8][4];
#pragma unroll
    for (int mt = 0; mt < 2; mt++)
#pragma unroll
        for (int nt = 0; nt < 8; nt++)
#pragma unroll
            for (int q = 0; q < 4; q++) acc[mt][nt][q] = 0.f;

    int curBuf = 0, stgBuf = 2;                    // buf of chunk gc / gc+2

#pragma unroll 1
    for (int gc = 0; gc < 48; gc++) {
        // chunk gc's copy complete (gc+1 may still be in flight)
        if (gc < 47) { CP_WAIT1(); } else { CP_WAIT0(); }
        __syncthreads();   // publish buf curBuf; all warps done with chunk gc-1

        // stage 2 ahead into buf (gc+2)%3 == (gc-1)%3 (readers finished above)
        if (gc + 2 < 48) {
            stageB(gc + 2, stgBuf);
            CP_COMMIT();
            if (++stgBuf == N_BUF) stgBuf = 0;
        }

        // ---- compute chunk gc (k16) ----
        const uint32_t koffA = (gc & 15) * 32;
        uint32_t aH[2][4], aL[2][4];
#pragma unroll
        for (int mt = 0; mt < 2; mt++) {
            LDSM_X4(aH[mt][0], aH[mt][1], aH[mt][2], aH[mt][3],
                    aBaseH[mt] + koffA);
            LDSM_X4(aL[mt][0], aL[mt][1], aL[mt][2], aL[mt][3],
                    aBaseH[mt] + OFF_ALO + koffA);
        }
        const uint32_t bk = bBase + curBuf * B_CHUNK_B;
        if (++curBuf == N_BUF) curBuf = 0;
#pragma unroll
        for (int op = 0; op < 4; op++) {
            uint32_t bh0, bh1, bh2, bh3, bl0, bl1, bl2, bl3;
            LDSM_X4(bh0, bh1, bh2, bh3, bk + op * (16 * B_STRIDE));
            LDSM_X4(bl0, bl1, bl2, bl3, bk + op * (16 * B_STRIDE) + B_PLANE_B);
#pragma unroll
            for (int mt = 0; mt < 2; mt++) {
                mma_bf16(acc[mt][2 * op],     aH[mt], bh0, bh1);
                mma_bf16(acc[mt][2 * op],     aL[mt], bh0, bh1);
                mma_bf16(acc[mt][2 * op],     aH[mt], bl0, bl1);
                mma_bf16(acc[mt][2 * op + 1], aH[mt], bh2, bh3);
                mma_bf16(acc[mt][2 * op + 1], aL[mt], bh2, bh3);
                mma_bf16(acc[mt][2 * op + 1], aH[mt], bl2, bl3);
            }
        }

        // ---- layer epilogue (every 16 chunks) ----
        if ((gc & 15) == 15) {
            const int l = gc >> 4;
            const float* sB = sBias + l * 256;
            __syncthreads();   // all compute done before A rewrite
            if (l < 2) {
#pragma unroll
                for (int mt = 0; mt < 2; mt++) {
#pragma unroll
                    for (int nt = 0; nt < 8; nt++) {
                        int col = wn * 64 + nt * 8 + tg * 2;
                        float b0 = sB[col], b1 = sB[col + 1];
                        int rlo = wm * 32 + mt * 16 + g;
#pragma unroll
                        for (int half = 0; half < 2; half++) {
                            int r = rlo + half * 8;
                            float v0 = fmaxf(acc[mt][nt][2 * half]     + b0, 0.f);
                            float v1 = fmaxf(acc[mt][nt][2 * half + 1] + b1, 0.f);
                            __nv_bfloat16 h0 = __float2bfloat16(v0);
                            __nv_bfloat16 h1 = __float2bfloat16(v1);
                            uint32_t hv = pack_bf2(h0, h1);
                            uint32_t lv = pack_bf2(
                                __float2bfloat16(v0 - __bfloat162float(h0)),
                                __float2bfloat16(v1 - __bfloat162float(h1)));
                            char* pa = smc + OFF_AHI + r * A_STR_B + col * 2;
                            *reinterpret_cast<uint32_t*>(pa) = hv;
                            *reinterpret_cast<uint32_t*>(pa + OFF_ALO) = lv;
                            acc[mt][nt][2 * half] = 0.f;
                            acc[mt][nt][2 * half + 1] = 0.f;
                        }
                    }
                }
                // next chunk's top barrier publishes the A rewrite
            } else {
#pragma unroll
                for (int mt = 0; mt < 2; mt++) {
#pragma unroll
                    for (int half = 0; half < 2; half++) {
                        int r = wm * 32 + mt * 16 + g + half * 8;
                        float* orow = out + (size_t)sOrig[r] * D;
#pragma unroll
                        for (int nt = 0; nt < 8; nt++) {
                            int col = wn * 64 + nt * 8 + tg * 2;
                            float2 v;
                            v.x = fmaxf(acc[mt][nt][2 * half]     + sB[col],     0.f);
                            v.y = fmaxf(acc[mt][nt][2 * half + 1] + sB[col + 1], 0.f);
                            *reinterpret_cast<float2*>(orow + col) = v;
                        }
                    }
                }
            }
        }
    }
}

// ======================= FFMA2 fallback for mixed 128-tiles =======================
constexpr int FTILE = 64;
constexpr int FKC = 16;
constexpr int FSTR = D + 8;
constexpr int FOFF_SX = 0;
constexpr int FOFF_SW = FOFF_SX + FTILE * FSTR;
constexpr int FOFF_BLEAF = FOFF_SW + FKC * D;
constexpr int FOFF_BMID = FOFF_BLEAF + LEAVES * D;
constexpr int FOFF_BROOT = FOFF_BMID + MID * D;
constexpr int FOFF_ORIG = FOFF_BROOT + D;
constexpr int FOFF_E = FOFF_ORIG + FTILE;
constexpr int FOFF_MM = FOFF_E + FTILE;
constexpr int FB_BYTES = (FOFF_MM + 2) * (int)sizeof(float);

#define FMA_F32X2(d, a, b, c) \
    asm("fma.rn.f32x2 %0, %1, %2, %3;" : "=l"(d) : "l"(a), "l"(b), "l"(c))
#define PACK2(d, xx) \
    asm("mov.b64 %0, {%1, %1};" : "=l"(d) : "r"(xx))

template <bool MASKED>
__device__ __forceinline__
void fb_gemm(const float* __restrict__ Wglob, float* sW, const float* sX,
             const float m[8], u64 (&acc2)[8][4], int tid, int r0, int c0)
{
#pragma unroll 1
    for (int kc = 0; kc < D; kc += FKC) {
        __syncthreads();
        const float4* wg4 = reinterpret_cast<const float4*>(Wglob + (size_t)kc * D);
        float4* sW4 = reinterpret_cast<float4*>(sW);
#pragma unroll
        for (int i = 0; i < (FKC * D / 4) / 256; i++)
            sW4[tid + i * 256] = wg4[tid + i * 256];
        __syncthreads();
#pragma unroll
        for (int k4 = 0; k4 < FKC; k4 += 4) {
            float4 a4[8];
#pragma unroll
            for (int i = 0; i < 8; i++) {
                a4[i] = *reinterpret_cast<const float4*>(&sX[(r0 + i) * FSTR + kc + k4]);
                if (MASKED) {
                    a4[i].x *= m[i]; a4[i].y *= m[i];
                    a4[i].z *= m[i]; a4[i].w *= m[i];
                }
            }
#pragma unroll
            for (int kk = 0; kk < 4; kk++) {
                const ulonglong2* bp =
                    reinterpret_cast<const ulonglong2*>(&sW[(k4 + kk) * D + c0]);
                ulonglong2 b01 = bp[0];
                ulonglong2 b23 = bp[1];
#pragma unroll
                for (int i = 0; i < 8; i++) {
                    float av = (kk == 0) ? a4[i].x : (kk == 1) ? a4[i].y
                             : (kk == 2) ? a4[i].z : a4[i].w;
                    u64 a2;
                    PACK2(a2, __float_as_uint(av));
                    FMA_F32X2(acc2[i][0], a2, b01.x, acc2[i][0]);
                    FMA_F32X2(acc2[i][1], a2, b01.y, acc2[i][1]);
                    FMA_F32X2(acc2[i][2], a2, b23.x, acc2[i][2]);
                    FMA_F32X2(acc2[i][3], a2, b23.y, acc2[i][3]);
                }
            }
        }
    }
}

__global__ void __launch_bounds__(256, 2)
fallback_kernel(const float* __restrict__ x,
                const float* __restrict__ W_leaf, const float* __restrict__ b_leaf,
                const float* __restrict__ W_mid,  const float* __restrict__ b_mid,
                const float* __restrict__ W_root, const float* __restrict__ b_root,
                float* __restrict__ out)
{
    const size_t t128 = (size_t)(blockIdx.x >> 1) * 128;
    if (g_idx[g_perm[t128]] == g_idx[g_perm[t128 + 127]]) return;

    extern __shared__ float sm[];
    float* sX = sm + FOFF_SX;  float* sW = sm + FOFF_SW;
    float* sBlf = sm + FOFF_BLEAF;  float* sBmd = sm + FOFF_BMID;
    float* sBrt = sm + FOFF_BROOT;
    int* sOrig = reinterpret_cast<int*>(sm + FOFF_ORIG);
    int* sE = reinterpret_cast<int*>(sm + FOFF_E);
    int* sMM = reinterpret_cast<int*>(sm + FOFF_MM);

    const int tid = threadIdx.x;
    const size_t row0 = (size_t)blockIdx.x * FTILE;
    const int tx = tid & 31, ty = tid >> 5;
    const int r0 = ty * 8, c0 = tx * 8;

    if (tid < FTILE) {
        int orig = g_perm[row0 + tid];
        sOrig[tid] = orig;
        sE[tid] = g_idx[orig];
    }
    if (tid == FTILE) { sMM[0] = LEAVES; sMM[1] = -1; }
    __syncthreads();

#pragma unroll
    for (int i = 0; i < (FTILE * D / 4) / 256; i++) {
        int li = tid + i * 256;
        int r = li / (D / 4), c4 = li % (D / 4);
        const float4* src = reinterpret_cast<const float4*>(x + (size_t)sOrig[r] * D);
        float4 v = src[c4];
        float* dst = &sX[r * FSTR + c4 * 4];
        dst[0] = v.x; dst[1] = v.y; dst[2] = v.z; dst[3] = v.w;
    }
    for (int i = tid; i < LEAVES * D; i += 256) sBlf[i] = b_leaf[i];
    for (int i = tid; i < MID * D;    i += 256) sBmd[i] = b_mid[i];
    for (int i = tid; i < D;          i += 256) sBrt[i] = b_root[i];
    if (tid < FTILE) {
        atomicMin(&sMM[0], sE[tid]);
        atomicMax(&sMM[1], sE[tid]);
    }
    __syncthreads();

    const int emin = sMM[0], emax = sMM[1];
    u64 acc2[8][4];
#pragma unroll
    for (int i = 0; i < 8; i++)
#pragma unroll
        for (int j = 0; j < 4; j++) acc2[i][j] = 0ull;
    float m[8];

    if (emin == emax) {
        fb_gemm<false>(W_leaf + (size_t)emin * D * D, sW, sX, m, acc2, tid, r0, c0);
    } else {
        for (int e = emin; e <= emax; e++) {
#pragma unroll
            for (int i = 0; i < 8; i++) m[i] = (sE[r0 + i] == e) ? 1.f : 0.f;
            fb_gemm<true>(W_leaf + (size_t)e * D * D, sW, sX, m, acc2, tid, r0, c0);
        }
    }
#pragma unroll
    for (int i = 0; i < 8; i++) {
        int e = sE[r0 + i];
#pragma unroll
        for (int p = 0; p < 4; p++) {
            U64F2 u; u.u = acc2[i][p];
            sX[(r0 + i) * FSTR + c0 + 2 * p]     = fmaxf(u.f.x + sBlf[e * D + c0 + 2 * p], 0.f);
            sX[(r0 + i) * FSTR + c0 + 2 * p + 1] = fmaxf(u.f.y + sBlf[e * D + c0 + 2 * p + 1], 0.f);
            acc2[i][p] = 0ull;
        }
    }

    const int pmin = emin >> 1, pmax = emax >> 1;
    if (pmin == pmax) {
        fb_gemm<false>(W_mid + (size_t)pmin * D * D, sW, sX, m, acc2, tid, r0, c0);
    } else {
        for (int p = pmin; p <= pmax; p++) {
#pragma unroll
            for (int i = 0; i < 8; i++) m[i] = ((sE[r0 + i] >> 1) == p) ? 1.f : 0.f;
            fb_gemm<true>(W_mid + (size_t)p * D * D, sW, sX, m, acc2, tid, r0, c0);
        }
    }
#pragma unroll
    for (int i = 0; i < 8; i++) {
        int pp = sE[r0 + i] >> 1;
#pragma unroll
        for (int p = 0; p < 4; p++) {
            U64F2 u; u.u = acc2[i][p];
            sX[(r0 + i) * FSTR + c0 + 2 * p]     = fmaxf(u.f.x + sBmd[pp * D + c0 + 2 * p], 0.f);
            sX[(r0 + i) * FSTR + c0 + 2 * p + 1] = fmaxf(u.f.y + sBmd[pp * D + c0 + 2 * p + 1], 0.f);
            acc2[i][p] = 0ull;
        }
    }

    fb_gemm<false>(W_root, sW, sX, m, acc2, tid, r0, c0);
#pragma unroll
    for (int i = 0; i < 8; i++) {
        float v[8];
#pragma unroll
        for (int p = 0; p < 4; p++) {
            U64F2 u; u.u = acc2[i][p];
            v[2 * p]     = fmaxf(u.f.x + sBrt[c0 + 2 * p],     0.f);
            v[2 * p + 1] = fmaxf(u.f.y + sBrt[c0 + 2 * p + 1], 0.f);
        }
        float4* o = reinterpret_cast<float4*>(out + (size_t)sOrig[r0 + i] * D + c0);
        o[0] = make_float4(v[0], v[1], v[2], v[3]);
        o[1] = make_float4(v[4], v[5], v[6], v[7]);
    }
}

// ======================= launch =======================
extern "C" void kernel_launch(void* const* d_in, const int* in_sizes, int n_in,
                              void* d_out, int out_size)
{
    const float* x      = (const float*)d_in[0];
    const float* Wg     = (const float*)d_in[1];
    const float* bg     = (const float*)d_in[2];
    const float* W_leaf = (const float*)d_in[3];
    const float* b_leaf = (const float*)d_in[4];
    const float* W_mid  = (const float*)d_in[5];
    const float* b_mid  = (const float*)d_in[6];
    const float* W_root = (const float*)d_in[7];
    const float* b_root = (const float*)d_in[8];
    float* out = (float*)d_out;

    cudaFuncSetAttribute(gate_kernel,
                         cudaFuncAttributeMaxDynamicSharedMemorySize, GATE_BYTES);
    cudaFuncSetAttribute(tree_mma_kernel,
                         cudaFuncAttributeMaxDynamicSharedMemorySize, MMA_SMEM);
    cudaFuncSetAttribute(fallback_kernel,
                         cudaFuncAttributeMaxDynamicSharedMemorySize, FB_BYTES);

    init_kernel<<<1, 32>>>();
    prep_w_kernel<<<7 * 65536 / 256, 256>>>(W_leaf, W_mid, W_root);
    gate_kernel<<<NB / GTILE, 256, GATE_BYTES>>>(x, Wg, bg);
    scan_kernel<<<1, 1>>>();
    scatter_kernel<<<NB / 256, 256>>>();
    tree_mma_kernel<<<NB / 128, 512, MMA_SMEM>>>(x, b_leaf, b_mid, b_root, out);
    fallback_kernel<<<NB / FTILE, 256, FB_BYTES>>>(
        x, W_leaf, b_leaf, W_mid, b_mid, W_root, b_root, out);
}

// round 11
// speedup vs baseline: 1.1406x; 1.1000x over previous
#include <cuda_runtime.h>
#include <cuda_bf16.h>
#include <cuda_fp16.h>
#include <cstdint>

#define NB      131072
#define D       256
#define LEAVES  4
#define MID     2

typedef unsigned long long u64;
union U64F2 { u64 u; float2 f; };

__device__ __forceinline__ uint32_t smem_u32(const void* p) {
    uint32_t a;
    asm("{ .reg .u64 t; cvta.to.shared.u64 t, %1; cvt.u32.u64 %0, t; }"
        : "=r"(a) : "l"(p));
    return a;
}

__device__ __forceinline__ uint32_t pack_bf2(__nv_bfloat16 a, __nv_bfloat16 b) {
    __nv_bfloat162 p = __halves2bfloat162(a, b);
    return *reinterpret_cast<uint32_t*>(&p);
}
__device__ __forceinline__ uint32_t pack_h2(__half a, __half b) {
    __half2 p = __halves2half2(a, b);
    return *reinterpret_cast<uint32_t*>(&p);
}

// portable HMMA, bf16 and fp16 variants (both m16n8k16, f32 acc)
__device__ __forceinline__
void mma_bf16(float* c, const uint32_t a[4], uint32_t b0, uint32_t b1)
{
    asm("mma.sync.aligned.m16n8k16.row.col.f32.bf16.bf16.f32 "
        "{%0,%1,%2,%3}, {%4,%5,%6,%7}, {%8,%9}, {%0,%1,%2,%3};"
        : "+f"(c[0]), "+f"(c[1]), "+f"(c[2]), "+f"(c[3])
        : "r"(a[0]), "r"(a[1]), "r"(a[2]), "r"(a[3]), "r"(b0), "r"(b1));
}
__device__ __forceinline__
void mma_f16(float* c, const uint32_t a[4], uint32_t b0, uint32_t b1)
{
    asm("mma.sync.aligned.m16n8k16.row.col.f32.f16.f16.f32 "
        "{%0,%1,%2,%3}, {%4,%5,%6,%7}, {%8,%9}, {%0,%1,%2,%3};"
        : "+f"(c[0]), "+f"(c[1]), "+f"(c[2]), "+f"(c[3])
        : "r"(a[0]), "r"(a[1]), "r"(a[2]), "r"(a[3]), "r"(b0), "r"(b1));
}

#define LDSM_X4(r0, r1, r2, r3, addr)                                        \
    asm volatile("ldmatrix.sync.aligned.m8n8.x4.shared.b16 {%0,%1,%2,%3}, [%4];" \
        : "=r"(r0), "=r"(r1), "=r"(r2), "=r"(r3) : "r"(addr))

// ======================= global scratch =======================
__device__ int g_idx[NB];
__device__ int g_perm[NB];
__device__ int g_hist[LEAVES];
__device__ int g_base[LEAVES];
// 7 mats x [fp16(W) plane | bf16(W - fp16(W)) plane] x [n=256][k=256]
__device__ __align__(16) unsigned short g_wimg[7 * 2 * 65536];

// ======================= gate / sort =======================
constexpr int GTILE = 64;
constexpr int GSTR  = D + 8;
constexpr int GOFF_SX  = 0;
constexpr int GOFF_WG  = GOFF_SX + GTILE * GSTR;
constexpr int GOFF_LOG = GOFF_WG + D * LEAVES;
constexpr int GOFF_H   = GOFF_LOG + GTILE * LEAVES;
constexpr int GATE_BYTES = (GOFF_H + LEAVES) * (int)sizeof(float);

__global__ void init_kernel() {
    if (threadIdx.x < LEAVES) g_hist[threadIdx.x] = 0;
}

__global__ void __launch_bounds__(256, 2)
gate_kernel(const float* __restrict__ x, const float* __restrict__ Wg,
            const float* __restrict__ bg)
{
    extern __shared__ float sm[];
    float* sX = sm + GOFF_SX;  float* sWg = sm + GOFF_WG;
    float* sLog = sm + GOFF_LOG;
    int* sH = reinterpret_cast<int*>(sm + GOFF_H);
    const int tid = threadIdx.x;
    const size_t row0 = (size_t)blockIdx.x * GTILE;

    const float4* xg = reinterpret_cast<const float4*>(x + row0 * D);
#pragma unroll
    for (int i = 0; i < (GTILE * D / 4) / 256; i++) {
        int li = tid + i * 256;
        int r = li / (D / 4), c4 = li % (D / 4);
        float4 v = xg[r * (D / 4) + c4];
        float* dst = &sX[r * GSTR + c4 * 4];
        dst[0] = v.x; dst[1] = v.y; dst[2] = v.z; dst[3] = v.w;
    }
    for (int i = tid; i < D * LEAVES; i += 256) sWg[i] = Wg[i];
    if (tid < LEAVES) sH[tid] = 0;
    __syncthreads();
    {
        int r = tid & (GTILE - 1);
        int e = tid >> 6;
        float acc = bg[e];
        const float* xr = &sX[r * GSTR];
#pragma unroll 8
        for (int d = 0; d < D; d++) acc = fmaf(xr[d], sWg[d * LEAVES + e], acc);
        sLog[r * LEAVES + e] = acc;
    }
    __syncthreads();
    if (tid < GTILE) {
        float best = sLog[tid * LEAVES];
        int bi = 0;
#pragma unroll
        for (int e = 1; e < LEAVES; e++) {
            float v = sLog[tid * LEAVES + e];
            if (v > best) { best = v; bi = e; }
        }
        g_idx[row0 + tid] = bi;
        atomicAdd(&sH[bi], 1);
    }
    __syncthreads();
    if (tid < LEAVES) atomicAdd(&g_hist[tid], sH[tid]);
}

__global__ void scan_kernel() {
    int b = 0;
    for (int e = 0; e < LEAVES; e++) { g_base[e] = b; b += g_hist[e]; }
}

__global__ void scatter_kernel() {
    __shared__ int cnt[LEAVES];
    __shared__ int boff[LEAVES];
    const int tid = threadIdx.x;
    const int r = blockIdx.x * blockDim.x + tid;
    if (tid < LEAVES) cnt[tid] = 0;
    __syncthreads();
    int e = g_idx[r];
    int my = atomicAdd(&cnt[e], 1);
    __syncthreads();
    if (tid < LEAVES) boff[tid] = atomicAdd(&g_base[tid], cnt[tid]);
    __syncthreads();
    g_perm[boff[e] + my] = r;
}

// == weight prep: fp32 W[k][n] -> plane0 fp16(W)[n][k], plane1 bf16(W-fp16(W)) ==
__global__ void prep_w_kernel(const float* __restrict__ Wl,
                              const float* __restrict__ Wm,
                              const float* __restrict__ Wr)
{
    int gid = blockIdx.x * 256 + threadIdx.x;      // 7*65536 total
    int mat = gid >> 16;
    int rem = gid & 0xFFFF;
    int n = rem >> 8, k = rem & 255;
    float v;
    if (mat < 4)      v = Wl[mat * 65536 + k * 256 + n];
    else if (mat < 6) v = Wm[(mat - 4) * 65536 + k * 256 + n];
    else              v = Wr[k * 256 + n];
    __half h = __float2half_rn(v);
    float lof = v - __half2float(h);
    __nv_bfloat16 l = __float2bfloat16(lof);
    unsigned short* base = g_wimg + (size_t)mat * 131072;
    base[n * 256 + k]         = __half_as_ushort(h);
    base[65536 + n * 256 + k] = __bfloat16_as_ushort(l);
}

// ======= main mma.sync kernel (R7 skeleton, 2-product fp16+bf16corr) =======
constexpr int A_STR_B   = 264 * 2;                 // 528
constexpr int OFF_AHI   = 0;                       // fp16(value) plane
constexpr int OFF_ABF   = 67584;                   // bf16(value) plane
constexpr int OFF_B     = 135168;
constexpr int B_PLANE_B = 256 * 40 * 2;            // 20480 (80B rows, k32)
constexpr int B_BUF_B   = 2 * B_PLANE_B;           // 40960
constexpr int OFF_BIAS  = OFF_B + 2 * B_BUF_B;     // 217088
constexpr int OFF_ORIG  = OFF_BIAS + 768 * 4;      // 220160
constexpr int MMA_SMEM  = OFF_ORIG + 512;          // 220672

__global__ void __launch_bounds__(512, 1)
tree_mma_kernel(const float* __restrict__ x,
                const float* __restrict__ b_leaf,
                const float* __restrict__ b_mid,
                const float* __restrict__ b_root,
                float* __restrict__ out)
{
    extern __shared__ char smc[];
    int* sOrig = reinterpret_cast<int*>(smc + OFF_ORIG);
    float* sBias = reinterpret_cast<float*>(smc + OFF_BIAS);
    const uint32_t sbU = smem_u32(smc);

    const int tid = threadIdx.x;
    const int lane = tid & 31, w = tid >> 5;       // 16 warps
    const int wm = w & 3, wn = w >> 2;             // 4 x 4 warp grid
    const int g = lane >> 2, tg = lane & 3;
    const size_t row0 = (size_t)blockIdx.x * 128;

    if (tid < 128) sOrig[tid] = g_perm[row0 + tid];
    __syncthreads();
    const int eL = g_idx[sOrig[0]];
    if (eL != g_idx[sOrig[127]]) return;          // mixed tile -> fallback
    const int eM = eL >> 1;
    const int matIdx[3] = { eL, 4 + eM, 6 };

    for (int i = tid; i < 256; i += 512) {
        sBias[i]       = b_leaf[eL * 256 + i];
        sBias[256 + i] = b_mid[eM * 256 + i];
        sBias[512 + i] = b_root[i];
    }

    // ---- A init: thread -> (row tid>>2, 64-col segment tid&3) ----
    // plane0 = fp16(x), plane1 = bf16(x)
    {
        int r = tid >> 2, seg = tid & 3;
        const float4* xr = reinterpret_cast<const float4*>(
                               x + (size_t)sOrig[r] * D) + seg * 16;
        char* aH = smc + OFF_AHI + r * A_STR_B + seg * 128;
        char* aB = smc + OFF_ABF + r * A_STR_B + seg * 128;
#pragma unroll
        for (int i = 0; i < 16; i++) {
            float4 f = xr[i];
            uint2 hv, lv;
            hv.x = pack_h2(__float2half_rn(f.x), __float2half_rn(f.y));
            hv.y = pack_h2(__float2half_rn(f.z), __float2half_rn(f.w));
            lv.x = pack_bf2(__float2bfloat16(f.x), __float2bfloat16(f.y));
            lv.y = pack_bf2(__float2bfloat16(f.z), __float2bfloat16(f.w));
            *reinterpret_cast<uint2*>(aH + i * 8) = hv;
            *reinterpret_cast<uint2*>(aB + i * 8) = lv;
        }
    }

    // ---- stage B chunk 0 of layer 0 into buffer 0 ----
    {
        int p = tid >> 8, n = tid & 255;
        const uint4* src = reinterpret_cast<const uint4*>(
            g_wimg + (size_t)matIdx[0] * 131072 + p * 65536 + n * 256);
        uint4* dst = reinterpret_cast<uint4*>(
            smc + OFF_B + p * B_PLANE_B + n * 80);
        dst[0] = src[0]; dst[1] = src[1]; dst[2] = src[2]; dst[3] = src[3];
    }
    __syncthreads();

    // ldmatrix base addresses (byte offsets in shared space)
    uint32_t aBase[2];
#pragma unroll
    for (int mt = 0; mt < 2; mt++)
        aBase[mt] = sbU + OFF_AHI
                  + (wm * 32 + mt * 16 + (lane & 15)) * A_STR_B
                  + (lane >> 4) * 16;
    const uint32_t bBase = sbU + OFF_B
        + (wn * 64 + (lane & 7) + ((lane >> 4) << 3)) * 80
        + (((lane >> 3) & 1) << 4);

    float acc[2][8][4];
#pragma unroll
    for (int mt = 0; mt < 2; mt++)
#pragma unroll
        for (int nt = 0; nt < 8; nt++)
#pragma unroll
            for (int q = 0; q < 4; q++) acc[mt][nt][q] = 0.f;

    int cur = 0;
    const int pfp = tid >> 8, pfn = tid & 255;     // B staging coords

#pragma unroll 1
    for (int l = 0; l < 3; l++) {
#pragma unroll 1
        for (int kc = 0; kc < 8; kc++) {
            // prefetch next chunk (next layer's chunk 0 at boundaries)
            bool hasNext = (kc < 7) || (l < 2);
            uint4 pf0, pf1, pf2, pf3;
            if (hasNext) {
                int nl  = (kc < 7) ? l : l + 1;
                int nkc = (kc < 7) ? kc + 1 : 0;
                const uint4* src = reinterpret_cast<const uint4*>(
                    g_wimg + (size_t)matIdx[nl] * 131072 + pfp * 65536
                    + pfn * 256 + nkc * 32);
                pf0 = src[0]; pf1 = src[1]; pf2 = src[2]; pf3 = src[3];
            }

            // ---- compute 2 k16-steps on buffer `cur` ----
#pragma unroll
            for (int kk = 0; kk < 2; kk++) {
                const uint32_t koffA = kc * 64 + kk * 32;
                uint32_t aH[2][4], aB[2][4];
#pragma unroll
                for (int mt = 0; mt < 2; mt++) {
                    LDSM_X4(aH[mt][0], aH[mt][1], aH[mt][2], aH[mt][3],
                            aBase[mt] + koffA);
                    LDSM_X4(aB[mt][0], aB[mt][1], aB[mt][2], aB[mt][3],
                            aBase[mt] + (OFF_ABF - OFF_AHI) + koffA);
                }
                const uint32_t bk = bBase + cur * B_BUF_B + kk * 32;
#pragma unroll
                for (int op = 0; op < 4; op++) {
                    uint32_t bh0, bh1, bh2, bh3, bl0, bl1, bl2, bl3;
                    LDSM_X4(bh0, bh1, bh2, bh3, bk + op * (16 * 80));
                    LDSM_X4(bl0, bl1, bl2, bl3, bk + op * (16 * 80) + B_PLANE_B);
#pragma unroll
                    for (int mt = 0; mt < 2; mt++) {
                        mma_f16 (acc[mt][2 * op],     aH[mt], bh0, bh1);
                        mma_bf16(acc[mt][2 * op],     aB[mt], bl0, bl1);
                        mma_f16 (acc[mt][2 * op + 1], aH[mt], bh2, bh3);
                        mma_bf16(acc[mt][2 * op + 1], aB[mt], bl2, bl3);
                    }
                }
            }

            if (hasNext) {
                uint4* dst = reinterpret_cast<uint4*>(
                    smc + OFF_B + (cur ^ 1) * B_BUF_B + pfp * B_PLANE_B + pfn * 80);
                dst[0] = pf0; dst[1] = pf1; dst[2] = pf2; dst[3] = pf3;
            }
            __syncthreads();
            cur ^= 1;
        }

        // ---- epilogue ----
        const float* sB = sBias + l * 256;
        if (l < 2) {
            // bias + relu + store fp16/bf16 planes for next layer
#pragma unroll
            for (int mt = 0; mt < 2; mt++) {
#pragma unroll
                for (int nt = 0; nt < 8; nt++) {
                    int col = wn * 64 + nt * 8 + tg * 2;
                    float b0 = sB[col], b1 = sB[col + 1];
                    int rlo = wm * 32 + mt * 16 + g;
#pragma unroll
                    for (int half = 0; half < 2; half++) {
                        int r = rlo + half * 8;
                        float v0 = fmaxf(acc[mt][nt][2 * half]     + b0, 0.f);
                        float v1 = fmaxf(acc[mt][nt][2 * half + 1] + b1, 0.f);
                        uint32_t hv = pack_h2(__float2half_rn(v0),
                                              __float2half_rn(v1));
                        uint32_t lv = pack_bf2(__float2bfloat16(v0),
                                               __float2bfloat16(v1));
                        char* pa = smc + OFF_AHI + r * A_STR_B + col * 2;
                        *reinterpret_cast<uint32_t*>(pa) = hv;
                        *reinterpret_cast<uint32_t*>(pa + (OFF_ABF - OFF_AHI)) = lv;
                        acc[mt][nt][2 * half] = 0.f;
                        acc[mt][nt][2 * half + 1] = 0.f;
                    }
                }
            }
            __syncthreads();   // A rewrite visible before next layer
        } else {
            // bias + relu + scatter to original rows
#pragma unroll
            for (int mt = 0; mt < 2; mt++) {
#pragma unroll
                for (int half = 0; half < 2; half++) {
                    int r = wm * 32 + mt * 16 + g + half * 8;
                    float* orow = out + (size_t)sOrig[r] * D;
#pragma unroll
                    for (int nt = 0; nt < 8; nt++) {
                        int col = wn * 64 + nt * 8 + tg * 2;
                        float2 v;
                        v.x = fmaxf(acc[mt][nt][2 * half]     + sB[col],     0.f);
                        v.y = fmaxf(acc[mt][nt][2 * half + 1] + sB[col + 1], 0.f);
                        *reinterpret_cast<float2*>(orow + col) = v;
                    }
                }
            }
        }
    }
}

// ======================= FFMA2 fallback for mixed 128-tiles =======================
constexpr int FTILE = 64;
constexpr int FKC = 16;
constexpr int FSTR = D + 8;
constexpr int FOFF_SX = 0;
constexpr int FOFF_SW = FOFF_SX + FTILE * FSTR;
constexpr int FOFF_BLEAF = FOFF_SW + FKC * D;
constexpr int FOFF_BMID = FOFF_BLEAF + LEAVES * D;
constexpr int FOFF_BROOT = FOFF_BMID + MID * D;
constexpr int FOFF_ORIG = FOFF_BROOT + D;
constexpr int FOFF_E = FOFF_ORIG + FTILE;
constexpr int FOFF_MM = FOFF_E + FTILE;
constexpr int FB_BYTES = (FOFF_MM + 2) * (int)sizeof(float);

#define FMA_F32X2(d, a, b, c) \
    asm("fma.rn.f32x2 %0, %1, %2, %3;" : "=l"(d) : "l"(a), "l"(b), "l"(c))
#define PACK2(d, xx) \
    asm("mov.b64 %0, {%1, %1};" : "=l"(d) : "r"(xx))

template <bool MASKED>
__device__ __forceinline__
void fb_gemm(const float* __restrict__ Wglob, float* sW, const float* sX,
             const float m[8], u64 (&acc2)[8][4], int tid, int r0, int c0)
{
#pragma unroll 1
    for (int kc = 0; kc < D; kc += FKC) {
        __syncthreads();
        const float4* wg4 = reinterpret_cast<const float4*>(Wglob + (size_t)kc * D);
        float4* sW4 = reinterpret_cast<float4*>(sW);
#pragma unroll
        for (int i = 0; i < (FKC * D / 4) / 256; i++)
            sW4[tid + i * 256] = wg4[tid + i * 256];
        __syncthreads();
#pragma unroll
        for (int k4 = 0; k4 < FKC; k4 += 4) {
            float4 a4[8];
#pragma unroll
            for (int i = 0; i < 8; i++) {
                a4[i] = *reinterpret_cast<const float4*>(&sX[(r0 + i) * FSTR + kc + k4]);
                if (MASKED) {
                    a4[i].x *= m[i]; a4[i].y *= m[i];
                    a4[i].z *= m[i]; a4[i].w *= m[i];
                }
            }
#pragma unroll
            for (int kk = 0; kk < 4; kk++) {
                const ulonglong2* bp =
                    reinterpret_cast<const ulonglong2*>(&sW[(k4 + kk) * D + c0]);
                ulonglong2 b01 = bp[0];
                ulonglong2 b23 = bp[1];
#pragma unroll
                for (int i = 0; i < 8; i++) {
                    float av = (kk == 0) ? a4[i].x : (kk == 1) ? a4[i].y
                             : (kk == 2) ? a4[i].z : a4[i].w;
                    u64 a2;
                    PACK2(a2, __float_as_uint(av));
                    FMA_F32X2(acc2[i][0], a2, b01.x, acc2[i][0]);
                    FMA_F32X2(acc2[i][1], a2, b01.y, acc2[i][1]);
                    FMA_F32X2(acc2[i][2], a2, b23.x, acc2[i][2]);
                    FMA_F32X2(acc2[i][3], a2, b23.y, acc2[i][3]);
                }
            }
        }
    }
}

__global__ void __launch_bounds__(256, 2)
fallback_kernel(const float* __restrict__ x,
                const float* __restrict__ W_leaf, const float* __restrict__ b_leaf,
                const float* __restrict__ W_mid,  const float* __restrict__ b_mid,
                const float* __restrict__ W_root, const float* __restrict__ b_root,
                float* __restrict__ out)
{
    const size_t t128 = (size_t)(blockIdx.x >> 1) * 128;
    if (g_idx[g_perm[t128]] == g_idx[g_perm[t128 + 127]]) return;

    extern __shared__ float sm[];
    float* sX = sm + FOFF_SX;  float* sW = sm + FOFF_SW;
    float* sBlf = sm + FOFF_BLEAF;  float* sBmd = sm + FOFF_BMID;
    float* sBrt = sm + FOFF_BROOT;
    int* sOrig = reinterpret_cast<int*>(sm + FOFF_ORIG);
    int* sE = reinterpret_cast<int*>(sm + FOFF_E);
    int* sMM = reinterpret_cast<int*>(sm + FOFF_MM);

    const int tid = threadIdx.x;
    const size_t row0 = (size_t)blockIdx.x * FTILE;
    const int tx = tid & 31, ty = tid >> 5;
    const int r0 = ty * 8, c0 = tx * 8;

    if (tid < FTILE) {
        int orig = g_perm[row0 + tid];
        sOrig[tid] = orig;
        sE[tid] = g_idx[orig];
    }
    if (tid == FTILE) { sMM[0] = LEAVES; sMM[1] = -1; }
    __syncthreads();

#pragma unroll
    for (int i = 0; i < (FTILE * D / 4) / 256; i++) {
        int li = tid + i * 256;
        int r = li / (D / 4), c4 = li % (D / 4);
        const float4* src = reinterpret_cast<const float4*>(x + (size_t)sOrig[r] * D);
        float4 v = src[c4];
        float* dst = &sX[r * FSTR + c4 * 4];
        dst[0] = v.x; dst[1] = v.y; dst[2] = v.z; dst[3] = v.w;
    }
    for (int i = tid; i < LEAVES * D; i += 256) sBlf[i] = b_leaf[i];
    for (int i = tid; i < MID * D;    i += 256) sBmd[i] = b_mid[i];
    for (int i = tid; i < D;          i += 256) sBrt[i] = b_root[i];
    if (tid < FTILE) {
        atomicMin(&sMM[0], sE[tid]);
        atomicMax(&sMM[1], sE[tid]);
    }
    __syncthreads();

    const int emin = sMM[0], emax = sMM[1];
    u64 acc2[8][4];
#pragma unroll
    for (int i = 0; i < 8; i++)
#pragma unroll
        for (int j = 0; j < 4; j++) acc2[i][j] = 0ull;
    float m[8];

    if (emin == emax) {
        fb_gemm<false>(W_leaf + (size_t)emin * D * D, sW, sX, m, acc2, tid, r0, c0);
    } else {
        for (int e = emin; e <= emax; e++) {
#pragma unroll
            for (int i = 0; i < 8; i++) m[i] = (sE[r0 + i] == e) ? 1.f : 0.f;
            fb_gemm<true>(W_leaf + (size_t)e * D * D, sW, sX, m, acc2, tid, r0, c0);
        }
    }
#pragma unroll
    for (int i = 0; i < 8; i++) {
        int e = sE[r0 + i];
#pragma unroll
        for (int p = 0; p < 4; p++) {
            U64F2 u; u.u = acc2[i][p];
            sX[(r0 + i) * FSTR + c0 + 2 * p]     = fmaxf(u.f.x + sBlf[e * D + c0 + 2 * p], 0.f);
            sX[(r0 + i) * FSTR + c0 + 2 * p + 1] = fmaxf(u.f.y + sBlf[e * D + c0 + 2 * p + 1], 0.f);
            acc2[i][p] = 0ull;
        }
    }

    const int pmin = emin >> 1, pmax = emax >> 1;
    if (pmin == pmax) {
        fb_gemm<false>(W_mid + (size_t)pmin * D * D, sW, sX, m, acc2, tid, r0, c0);
    } else {
        for (int p = pmin; p <= pmax; p++) {
#pragma unroll
            for (int i = 0; i < 8; i++) m[i] = ((sE[r0 + i] >> 1) == p) ? 1.f : 0.f;
            fb_gemm<true>(W_mid + (size_t)p * D * D, sW, sX, m, acc2, tid, r0, c0);
        }
    }
#pragma unroll
    for (int i = 0; i < 8; i++) {
        int pp = sE[r0 + i] >> 1;
#pragma unroll
        for (int p = 0; p < 4; p++) {
            U64F2 u; u.u = acc2[i][p];
            sX[(r0 + i) * FSTR + c0 + 2 * p]     = fmaxf(u.f.x + sBmd[pp * D + c0 + 2 * p], 0.f);
            sX[(r0 + i) * FSTR + c0 + 2 * p + 1] = fmaxf(u.f.y + sBmd[pp * D + c0 + 2 * p + 1], 0.f);
            acc2[i][p] = 0ull;
        }
    }

    fb_gemm<false>(W_root, sW, sX, m, acc2, tid, r0, c0);
#pragma unroll
    for (int i = 0; i < 8; i++) {
        float v[8];
#pragma unroll
        for (int p = 0; p < 4; p++) {
            U64F2 u; u.u = acc2[i][p];
            v[2 * p]     = fmaxf(u.f.x + sBrt[c0 + 2 * p],     0.f);
            v[2 * p + 1] = fmaxf(u.f.y + sBrt[c0 + 2 * p + 1], 0.f);
        }
        float4* o = reinterpret_cast<float4*>(out + (size_t)sOrig[r0 + i] * D + c0);
        o[0] = make_float4(v[0], v[1], v[2], v[3]);
        o[1] = make_float4(v[4], v[5], v[6], v[7]);
    }
}

// ======================= launch =======================
extern "C" void kernel_launch(void* const* d_in, const int* in_sizes, int n_in,
                              void* d_out, int out_size)
{
    const float* x      = (const float*)d_in[0];
    const float* Wg     = (const float*)d_in[1];
    const float* bg     = (const float*)d_in[2];
    const float* W_leaf = (const float*)d_in[3];
    const float* b_leaf = (const float*)d_in[4];
    const float* W_mid  = (const float*)d_in[5];
    const float* b_mid  = (const float*)d_in[6];
    const float* W_root = (const float*)d_in[7];
    const float* b_root = (const float*)d_in[8];
    float* out = (float*)d_out;

    cudaFuncSetAttribute(gate_kernel,
                         cudaFuncAttributeMaxDynamicSharedMemorySize, GATE_BYTES);
    cudaFuncSetAttribute(tree_mma_kernel,
                         cudaFuncAttributeMaxDynamicSharedMemorySize, MMA_SMEM);
    cudaFuncSetAttribute(fallback_kernel,
                         cudaFuncAttributeMaxDynamicSharedMemorySize, FB_BYTES);

    init_kernel<<<1, 32>>>();
    prep_w_kernel<<<7 * 65536 / 256, 256>>>(W_leaf, W_mid, W_root);
    gate_kernel<<<NB / GTILE, 256, GATE_BYTES>>>(x, Wg, bg);
    scan_kernel<<<1, 1>>>();
    scatter_kernel<<<NB / 256, 256>>>();
    tree_mma_kernel<<<NB / 128, 512, MMA_SMEM>>>(x, b_leaf, b_mid, b_root, out);
    fallback_kernel<<<NB / FTILE, 256, FB_BYTES>>>(
        x, W_leaf, b_leaf, W_mid, b_mid, W_root, b_root, out);
}

// round 12
// speedup vs baseline: 1.3375x; 1.1726x over previous
#include <cuda_runtime.h>
#include <cuda_bf16.h>
#include <cuda_fp16.h>
#include <cstdint>

#define NB      131072
#define D       256
#define LEAVES  4
#define MID     2

typedef unsigned long long u64;
union U64F2 { u64 u; float2 f; };

__device__ __forceinline__ uint32_t smem_u32(const void* p) {
    uint32_t a;
    asm("{ .reg .u64 t; cvta.to.shared.u64 t, %1; cvt.u32.u64 %0, t; }"
        : "=r"(a) : "l"(p));
    return a;
}

__device__ __forceinline__ uint32_t pack_bf2(__nv_bfloat16 a, __nv_bfloat16 b) {
    __nv_bfloat162 p = __halves2bfloat162(a, b);
    return *reinterpret_cast<uint32_t*>(&p);
}
__device__ __forceinline__ uint32_t pack_h2(__half a, __half b) {
    __half2 p = __halves2half2(a, b);
    return *reinterpret_cast<uint32_t*>(&p);
}

// portable HMMA, bf16 and fp16 variants (both m16n8k16, f32 acc)
__device__ __forceinline__
void mma_bf16(float* c, const uint32_t a[4], uint32_t b0, uint32_t b1)
{
    asm("mma.sync.aligned.m16n8k16.row.col.f32.bf16.bf16.f32 "
        "{%0,%1,%2,%3}, {%4,%5,%6,%7}, {%8,%9}, {%0,%1,%2,%3};"
        : "+f"(c[0]), "+f"(c[1]), "+f"(c[2]), "+f"(c[3])
        : "r"(a[0]), "r"(a[1]), "r"(a[2]), "r"(a[3]), "r"(b0), "r"(b1));
}
__device__ __forceinline__
void mma_f16(float* c, const uint32_t a[4], uint32_t b0, uint32_t b1)
{
    asm("mma.sync.aligned.m16n8k16.row.col.f32.f16.f16.f32 "
        "{%0,%1,%2,%3}, {%4,%5,%6,%7}, {%8,%9}, {%0,%1,%2,%3};"
        : "+f"(c[0]), "+f"(c[1]), "+f"(c[2]), "+f"(c[3])
        : "r"(a[0]), "r"(a[1]), "r"(a[2]), "r"(a[3]), "r"(b0), "r"(b1));
}

#define LDSM_X4(r0, r1, r2, r3, addr)                                        \
    asm volatile("ldmatrix.sync.aligned.m8n8.x4.shared.b16 {%0,%1,%2,%3}, [%4];" \
        : "=r"(r0), "=r"(r1), "=r"(r2), "=r"(r3) : "r"(addr))

// ======================= global scratch =======================
__device__ int g_idx[NB];
__device__ int g_perm[NB];
__device__ int g_hist[LEAVES];
__device__ int g_base[LEAVES];
// CHUNK-MAJOR weight images: [mat(7)][kc(8)][plane(2)][n(256)][32 u16]
//   plane0 = fp16(W), plane1 = bf16(W - fp16(W));  B col-major per chunk.
// per mat: 8*2*256*32 = 131072 u16 (same total as before, re-ordered)
__device__ __align__(16) unsigned short g_wimg[7 * 131072];

// ======================= gate / sort =======================
constexpr int GTILE = 64;
constexpr int GSTR  = D + 8;
constexpr int GOFF_SX  = 0;
constexpr int GOFF_WG  = GOFF_SX + GTILE * GSTR;
constexpr int GOFF_LOG = GOFF_WG + D * LEAVES;
constexpr int GOFF_H   = GOFF_LOG + GTILE * LEAVES;
constexpr int GATE_BYTES = (GOFF_H + LEAVES) * (int)sizeof(float);

__global__ void init_kernel() {
    if (threadIdx.x < LEAVES) g_hist[threadIdx.x] = 0;
}

__global__ void __launch_bounds__(256, 2)
gate_kernel(const float* __restrict__ x, const float* __restrict__ Wg,
            const float* __restrict__ bg)
{
    extern __shared__ float sm[];
    float* sX = sm + GOFF_SX;  float* sWg = sm + GOFF_WG;
    float* sLog = sm + GOFF_LOG;
    int* sH = reinterpret_cast<int*>(sm + GOFF_H);
    const int tid = threadIdx.x;
    const size_t row0 = (size_t)blockIdx.x * GTILE;

    const float4* xg = reinterpret_cast<const float4*>(x + row0 * D);
#pragma unroll
    for (int i = 0; i < (GTILE * D / 4) / 256; i++) {
        int li = tid + i * 256;
        int r = li / (D / 4), c4 = li % (D / 4);
        float4 v = xg[r * (D / 4) + c4];
        float* dst = &sX[r * GSTR + c4 * 4];
        dst[0] = v.x; dst[1] = v.y; dst[2] = v.z; dst[3] = v.w;
    }
    for (int i = tid; i < D * LEAVES; i += 256) sWg[i] = Wg[i];
    if (tid < LEAVES) sH[tid] = 0;
    __syncthreads();
    {
        int r = tid & (GTILE - 1);
        int e = tid >> 6;
        float acc = bg[e];
        const float* xr = &sX[r * GSTR];
#pragma unroll 8
        for (int d = 0; d < D; d++) acc = fmaf(xr[d], sWg[d * LEAVES + e], acc);
        sLog[r * LEAVES + e] = acc;
    }
    __syncthreads();
    if (tid < GTILE) {
        float best = sLog[tid * LEAVES];
        int bi = 0;
#pragma unroll
        for (int e = 1; e < LEAVES; e++) {
            float v = sLog[tid * LEAVES + e];
            if (v > best) { best = v; bi = e; }
        }
        g_idx[row0 + tid] = bi;
        atomicAdd(&sH[bi], 1);
    }
    __syncthreads();
    if (tid < LEAVES) atomicAdd(&g_hist[tid], sH[tid]);
}

__global__ void scan_kernel() {
    int b = 0;
    for (int e = 0; e < LEAVES; e++) { g_base[e] = b; b += g_hist[e]; }
}

__global__ void scatter_kernel() {
    __shared__ int cnt[LEAVES];
    __shared__ int boff[LEAVES];
    const int tid = threadIdx.x;
    const int r = blockIdx.x * blockDim.x + tid;
    if (tid < LEAVES) cnt[tid] = 0;
    __syncthreads();
    int e = g_idx[r];
    int my = atomicAdd(&cnt[e], 1);
    __syncthreads();
    if (tid < LEAVES) boff[tid] = atomicAdd(&g_base[tid], cnt[tid]);
    __syncthreads();
    g_perm[boff[e] + my] = r;
}

// === weight prep: fp32 W[k][n] -> chunk-major fp16 / bf16-residual images ===
// dst u16 index: mat*131072 + kc*16384 + plane*8192 + n*32 + (k&31)
__global__ void prep_w_kernel(const float* __restrict__ Wl,
                              const float* __restrict__ Wm,
                              const float* __restrict__ Wr)
{
    int gid = blockIdx.x * 256 + threadIdx.x;      // 7*65536 total
    int mat = gid >> 16;
    int rem = gid & 0xFFFF;
    int n = rem >> 8, k = rem & 255;
    float v;
    if (mat < 4)      v = Wl[mat * 65536 + k * 256 + n];
    else if (mat < 6) v = Wm[(mat - 4) * 65536 + k * 256 + n];
    else              v = Wr[k * 256 + n];
    __half h = __float2half_rn(v);
    float lof = v - __half2float(h);
    __nv_bfloat16 l = __float2bfloat16(lof);
    size_t base = (size_t)mat * 131072 + (k >> 5) * 16384 + n * 32 + (k & 31);
    g_wimg[base]        = __half_as_ushort(h);
    g_wimg[base + 8192] = __bfloat16_as_ushort(l);
}

// ======= main mma.sync kernel (R11 skeleton, coalesced chunk loads) =======
constexpr int A_STR_B   = 264 * 2;                 // 528
constexpr int OFF_AHI   = 0;                       // fp16(value) plane
constexpr int OFF_ABF   = 67584;                   // bf16(value) plane
constexpr int OFF_B     = 135168;
constexpr int B_PLANE_B = 256 * 40 * 2;            // 20480 (80B rows, k32)
constexpr int B_BUF_B   = 2 * B_PLANE_B;           // 40960
constexpr int OFF_BIAS  = OFF_B + 2 * B_BUF_B;     // 217088
constexpr int OFF_ORIG  = OFF_BIAS + 768 * 4;      // 220160
constexpr int MMA_SMEM  = OFF_ORIG + 512;          // 220672

__global__ void __launch_bounds__(512, 1)
tree_mma_kernel(const float* __restrict__ x,
                const float* __restrict__ b_leaf,
                const float* __restrict__ b_mid,
                const float* __restrict__ b_root,
                float* __restrict__ out)
{
    extern __shared__ char smc[];
    int* sOrig = reinterpret_cast<int*>(smc + OFF_ORIG);
    float* sBias = reinterpret_cast<float*>(smc + OFF_BIAS);
    const uint32_t sbU = smem_u32(smc);

    const int tid = threadIdx.x;
    const int lane = tid & 31, w = tid >> 5;       // 16 warps
    const int wm = w & 3, wn = w >> 2;             // 4 x 4 warp grid
    const int g = lane >> 2, tg = lane & 3;
    const size_t row0 = (size_t)blockIdx.x * 128;

    if (tid < 128) sOrig[tid] = g_perm[row0 + tid];
    __syncthreads();
    const int eL = g_idx[sOrig[0]];
    if (eL != g_idx[sOrig[127]]) return;          // mixed tile -> fallback
    const int eM = eL >> 1;
    const int matIdx[3] = { eL, 4 + eM, 6 };

    for (int i = tid; i < 256; i += 512) {
        sBias[i]       = b_leaf[eL * 256 + i];
        sBias[256 + i] = b_mid[eM * 256 + i];
        sBias[512 + i] = b_root[i];
    }

    // ---- A init: thread -> (row tid>>2, 64-col segment tid&3) ----
    // plane0 = fp16(x), plane1 = bf16(x)
    {
        int r = tid >> 2, seg = tid & 3;
        const float4* xr = reinterpret_cast<const float4*>(
                               x + (size_t)sOrig[r] * D) + seg * 16;
        char* aH = smc + OFF_AHI + r * A_STR_B + seg * 128;
        char* aB = smc + OFF_ABF + r * A_STR_B + seg * 128;
#pragma unroll
        for (int i = 0; i < 16; i++) {
            float4 f = xr[i];
            uint2 hv, lv;
            hv.x = pack_h2(__float2half_rn(f.x), __float2half_rn(f.y));
            hv.y = pack_h2(__float2half_rn(f.z), __float2half_rn(f.w));
            lv.x = pack_bf2(__float2bfloat16(f.x), __float2bfloat16(f.y));
            lv.y = pack_bf2(__float2bfloat16(f.z), __float2bfloat16(f.w));
            *reinterpret_cast<uint2*>(aH + i * 8) = hv;
            *reinterpret_cast<uint2*>(aB + i * 8) = lv;
        }
    }

    // B staging coords: thread -> (plane sp, n-row sn); src 64B CONTIGUOUS
    const int sp = tid >> 8, sn = tid & 255;
    const uint32_t stgDstOff = sp * B_PLANE_B + sn * 80;

    // ---- stage B chunk 0 of layer 0 into buffer 0 (coalesced) ----
    {
        const uint4* src = reinterpret_cast<const uint4*>(
            g_wimg + (size_t)matIdx[0] * 131072 + sp * 8192 + sn * 32);
        uint4* dst = reinterpret_cast<uint4*>(smc + OFF_B + stgDstOff);
        dst[0] = src[0]; dst[1] = src[1]; dst[2] = src[2]; dst[3] = src[3];
    }
    __syncthreads();

    // ldmatrix base addresses (byte offsets in shared space)
    uint32_t aBase[2];
#pragma unroll
    for (int mt = 0; mt < 2; mt++)
        aBase[mt] = sbU + OFF_AHI
                  + (wm * 32 + mt * 16 + (lane & 15)) * A_STR_B
                  + (lane >> 4) * 16;
    const uint32_t bBase = sbU + OFF_B
        + (wn * 64 + (lane & 7) + ((lane >> 4) << 3)) * 80
        + (((lane >> 3) & 1) << 4);

    float acc[2][8][4];
#pragma unroll
    for (int mt = 0; mt < 2; mt++)
#pragma unroll
        for (int nt = 0; nt < 8; nt++)
#pragma unroll
            for (int q = 0; q < 4; q++) acc[mt][nt][q] = 0.f;

    int cur = 0;

#pragma unroll 1
    for (int l = 0; l < 3; l++) {
#pragma unroll 1
        for (int kc = 0; kc < 8; kc++) {
            // prefetch next chunk (next layer's chunk 0 at boundaries) — 64B contiguous
            bool hasNext = (kc < 7) || (l < 2);
            uint4 pf0, pf1, pf2, pf3;
            if (hasNext) {
                int nl  = (kc < 7) ? l : l + 1;
                int nkc = (kc < 7) ? kc + 1 : 0;
                const uint4* src = reinterpret_cast<const uint4*>(
                    g_wimg + (size_t)matIdx[nl] * 131072 + nkc * 16384
                    + sp * 8192 + sn * 32);
                pf0 = src[0]; pf1 = src[1]; pf2 = src[2]; pf3 = src[3];
            }

            // ---- compute 2 k16-steps on buffer `cur` ----
#pragma unroll
            for (int kk = 0; kk < 2; kk++) {
                const uint32_t koffA = kc * 64 + kk * 32;
                uint32_t aH[2][4], aB[2][4];
#pragma unroll
                for (int mt = 0; mt < 2; mt++) {
                    LDSM_X4(aH[mt][0], aH[mt][1], aH[mt][2], aH[mt][3],
                            aBase[mt] + koffA);
                    LDSM_X4(aB[mt][0], aB[mt][1], aB[mt][2], aB[mt][3],
                            aBase[mt] + (OFF_ABF - OFF_AHI) + koffA);
                }
                const uint32_t bk = bBase + cur * B_BUF_B + kk * 32;
#pragma unroll
                for (int op = 0; op < 4; op++) {
                    uint32_t bh0, bh1, bh2, bh3, bl0, bl1, bl2, bl3;
                    LDSM_X4(bh0, bh1, bh2, bh3, bk + op * (16 * 80));
                    LDSM_X4(bl0, bl1, bl2, bl3, bk + op * (16 * 80) + B_PLANE_B);
#pragma unroll
                    for (int mt = 0; mt < 2; mt++) {
                        mma_f16 (acc[mt][2 * op],     aH[mt], bh0, bh1);
                        mma_bf16(acc[mt][2 * op],     aB[mt], bl0, bl1);
                        mma_f16 (acc[mt][2 * op + 1], aH[mt], bh2, bh3);
                        mma_bf16(acc[mt][2 * op + 1], aB[mt], bl2, bl3);
                    }
                }
            }

            if (hasNext) {
                uint4* dst = reinterpret_cast<uint4*>(
                    smc + OFF_B + (cur ^ 1) * B_BUF_B + stgDstOff);
                dst[0] = pf0; dst[1] = pf1; dst[2] = pf2; dst[3] = pf3;
            }
            __syncthreads();
            cur ^= 1;
        }

        // ---- epilogue ----
        const float* sB = sBias + l * 256;
        if (l < 2) {
            // bias + relu + store fp16/bf16 planes for next layer
#pragma unroll
            for (int mt = 0; mt < 2; mt++) {
#pragma unroll
                for (int nt = 0; nt < 8; nt++) {
                    int col = wn * 64 + nt * 8 + tg * 2;
                    float b0 = sB[col], b1 = sB[col + 1];
                    int rlo = wm * 32 + mt * 16 + g;
#pragma unroll
                    for (int half = 0; half < 2; half++) {
                        int r = rlo + half * 8;
                        float v0 = fmaxf(acc[mt][nt][2 * half]     + b0, 0.f);
                        float v1 = fmaxf(acc[mt][nt][2 * half + 1] + b1, 0.f);
                        uint32_t hv = pack_h2(__float2half_rn(v0),
                                              __float2half_rn(v1));
                        uint32_t lv = pack_bf2(__float2bfloat16(v0),
                                               __float2bfloat16(v1));
                        char* pa = smc + OFF_AHI + r * A_STR_B + col * 2;
                        *reinterpret_cast<uint32_t*>(pa) = hv;
                        *reinterpret_cast<uint32_t*>(pa + (OFF_ABF - OFF_AHI)) = lv;
                        acc[mt][nt][2 * half] = 0.f;
                        acc[mt][nt][2 * half + 1] = 0.f;
                    }
                }
            }
            __syncthreads();   // A rewrite visible before next layer
        } else {
            // bias + relu + scatter to original rows
#pragma unroll
            for (int mt = 0; mt < 2; mt++) {
#pragma unroll
                for (int half = 0; half < 2; half++) {
                    int r = wm * 32 + mt * 16 + g + half * 8;
                    float* orow = out + (size_t)sOrig[r] * D;
#pragma unroll
                    for (int nt = 0; nt < 8; nt++) {
                        int col = wn * 64 + nt * 8 + tg * 2;
                        float2 v;
                        v.x = fmaxf(acc[mt][nt][2 * half]     + sB[col],     0.f);
                        v.y = fmaxf(acc[mt][nt][2 * half + 1] + sB[col + 1], 0.f);
                        *reinterpret_cast<float2*>(orow + col) = v;
                    }
                }
            }
        }
    }
}

// ======================= FFMA2 fallback for mixed 128-tiles =======================
constexpr int FTILE = 64;
constexpr int FKC = 16;
constexpr int FSTR = D + 8;
constexpr int FOFF_SX = 0;
constexpr int FOFF_SW = FOFF_SX + FTILE * FSTR;
constexpr int FOFF_BLEAF = FOFF_SW + FKC * D;
constexpr int FOFF_BMID = FOFF_BLEAF + LEAVES * D;
constexpr int FOFF_BROOT = FOFF_BMID + MID * D;
constexpr int FOFF_ORIG = FOFF_BROOT + D;
constexpr int FOFF_E = FOFF_ORIG + FTILE;
constexpr int FOFF_MM = FOFF_E + FTILE;
constexpr int FB_BYTES = (FOFF_MM + 2) * (int)sizeof(float);

#define FMA_F32X2(d, a, b, c) \
    asm("fma.rn.f32x2 %0, %1, %2, %3;" : "=l"(d) : "l"(a), "l"(b), "l"(c))
#define PACK2(d, xx) \
    asm("mov.b64 %0, {%1, %1};" : "=l"(d) : "r"(xx))

template <bool MASKED>
__device__ __forceinline__
void fb_gemm(const float* __restrict__ Wglob, float* sW, const float* sX,
             const float m[8], u64 (&acc2)[8][4], int tid, int r0, int c0)
{
#pragma unroll 1
    for (int kc = 0; kc < D; kc += FKC) {
        __syncthreads();
        const float4* wg4 = reinterpret_cast<const float4*>(Wglob + (size_t)kc * D);
        float4* sW4 = reinterpret_cast<float4*>(sW);
#pragma unroll
        for (int i = 0; i < (FKC * D / 4) / 256; i++)
            sW4[tid + i * 256] = wg4[tid + i * 256];
        __syncthreads();
#pragma unroll
        for (int k4 = 0; k4 < FKC; k4 += 4) {
            float4 a4[8];
#pragma unroll
            for (int i = 0; i < 8; i++) {
                a4[i] = *reinterpret_cast<const float4*>(&sX[(r0 + i) * FSTR + kc + k4]);
                if (MASKED) {
                    a4[i].x *= m[i]; a4[i].y *= m[i];
                    a4[i].z *= m[i]; a4[i].w *= m[i];
                }
            }
#pragma unroll
            for (int kk = 0; kk < 4; kk++) {
                const ulonglong2* bp =
                    reinterpret_cast<const ulonglong2*>(&sW[(k4 + kk) * D + c0]);
                ulonglong2 b01 = bp[0];
                ulonglong2 b23 = bp[1];
#pragma unroll
                for (int i = 0; i < 8; i++) {
                    float av = (kk == 0) ? a4[i].x : (kk == 1) ? a4[i].y
                             : (kk == 2) ? a4[i].z : a4[i].w;
                    u64 a2;
                    PACK2(a2, __float_as_uint(av));
                    FMA_F32X2(acc2[i][0], a2, b01.x, acc2[i][0]);
                    FMA_F32X2(acc2[i][1], a2, b01.y, acc2[i][1]);
                    FMA_F32X2(acc2[i][2], a2, b23.x, acc2[i][2]);
                    FMA_F32X2(acc2[i][3], a2, b23.y, acc2[i][3]);
                }
            }
        }
    }
}

__global__ void __launch_bounds__(256, 2)
fallback_kernel(const float* __restrict__ x,
                const float* __restrict__ W_leaf, const float* __restrict__ b_leaf,
                const float* __restrict__ W_mid,  const float* __restrict__ b_mid,
                const float* __restrict__ W_root, const float* __restrict__ b_root,
                float* __restrict__ out)
{
    const size_t t128 = (size_t)(blockIdx.x >> 1) * 128;
    if (g_idx[g_perm[t128]] == g_idx[g_perm[t128 + 127]]) return;

    extern __shared__ float sm[];
    float* sX = sm + FOFF_SX;  float* sW = sm + FOFF_SW;
    float* sBlf = sm + FOFF_BLEAF;  float* sBmd = sm + FOFF_BMID;
    float* sBrt = sm + FOFF_BROOT;
    int* sOrig = reinterpret_cast<int*>(sm + FOFF_ORIG);
    int* sE = reinterpret_cast<int*>(sm + FOFF_E);
    int* sMM = reinterpret_cast<int*>(sm + FOFF_MM);

    const int tid = threadIdx.x;
    const size_t row0 = (size_t)blockIdx.x * FTILE;
    const int tx = tid & 31, ty = tid >> 5;
    const int r0 = ty * 8, c0 = tx * 8;

    if (tid < FTILE) {
        int orig = g_perm[row0 + tid];
        sOrig[tid] = orig;
        sE[tid] = g_idx[orig];
    }
    if (tid == FTILE) { sMM[0] = LEAVES; sMM[1] = -1; }
    __syncthreads();

#pragma unroll
    for (int i = 0; i < (FTILE * D / 4) / 256; i++) {
        int li = tid + i * 256;
        int r = li / (D / 4), c4 = li % (D / 4);
        const float4* src = reinterpret_cast<const float4*>(x + (size_t)sOrig[r] * D);
        float4 v = src[c4];
        float* dst = &sX[r * FSTR + c4 * 4];
        dst[0] = v.x; dst[1] = v.y; dst[2] = v.z; dst[3] = v.w;
    }
    for (int i = tid; i < LEAVES * D; i += 256) sBlf[i] = b_leaf[i];
    for (int i = tid; i < MID * D;    i += 256) sBmd[i] = b_mid[i];
    for (int i = tid; i < D;          i += 256) sBrt[i] = b_root[i];
    if (tid < FTILE) {
        atomicMin(&sMM[0], sE[tid]);
        atomicMax(&sMM[1], sE[tid]);
    }
    __syncthreads();

    const int emin = sMM[0], emax = sMM[1];
    u64 acc2[8][4];
#pragma unroll
    for (int i = 0; i < 8; i++)
#pragma unroll
        for (int j = 0; j < 4; j++) acc2[i][j] = 0ull;
    float m[8];

    if (emin == emax) {
        fb_gemm<false>(W_leaf + (size_t)emin * D * D, sW, sX, m, acc2, tid, r0, c0);
    } else {
        for (int e = emin; e <= emax; e++) {
#pragma unroll
            for (int i = 0; i < 8; i++) m[i] = (sE[r0 + i] == e) ? 1.f : 0.f;
            fb_gemm<true>(W_leaf + (size_t)e * D * D, sW, sX, m, acc2, tid, r0, c0);
        }
    }
#pragma unroll
    for (int i = 0; i < 8; i++) {
        int e = sE[r0 + i];
#pragma unroll
        for (int p = 0; p < 4; p++) {
            U64F2 u; u.u = acc2[i][p];
            sX[(r0 + i) * FSTR + c0 + 2 * p]     = fmaxf(u.f.x + sBlf[e * D + c0 + 2 * p], 0.f);
            sX[(r0 + i) * FSTR + c0 + 2 * p + 1] = fmaxf(u.f.y + sBlf[e * D + c0 + 2 * p + 1], 0.f);
            acc2[i][p] = 0ull;
        }
    }

    const int pmin = emin >> 1, pmax = emax >> 1;
    if (pmin == pmax) {
        fb_gemm<false>(W_mid + (size_t)pmin * D * D, sW, sX, m, acc2, tid, r0, c0);
    } else {
        for (int p = pmin; p <= pmax; p++) {
#pragma unroll
            for (int i = 0; i < 8; i++) m[i] = ((sE[r0 + i] >> 1) == p) ? 1.f : 0.f;
            fb_gemm<true>(W_mid + (size_t)p * D * D, sW, sX, m, acc2, tid, r0, c0);
        }
    }
#pragma unroll
    for (int i = 0; i < 8; i++) {
        int pp = sE[r0 + i] >> 1;
#pragma unroll
        for (int p = 0; p < 4; p++) {
            U64F2 u; u.u = acc2[i][p];
            sX[(r0 + i) * FSTR + c0 + 2 * p]     = fmaxf(u.f.x + sBmd[pp * D + c0 + 2 * p], 0.f);
            sX[(r0 + i) * FSTR + c0 + 2 * p + 1] = fmaxf(u.f.y + sBmd[pp * D + c0 + 2 * p + 1], 0.f);
            acc2[i][p] = 0ull;
        }
    }

    fb_gemm<false>(W_root, sW, sX, m, acc2, tid, r0, c0);
#pragma unroll
    for (int i = 0; i < 8; i++) {
        float v[8];
#pragma unroll
        for (int p = 0; p < 4; p++) {
            U64F2 u; u.u = acc2[i][p];
            v[2 * p]     = fmaxf(u.f.x + sBrt[c0 + 2 * p],     0.f);
            v[2 * p + 1] = fmaxf(u.f.y + sBrt[c0 + 2 * p + 1], 0.f);
        }
        float4* o = reinterpret_cast<float4*>(out + (size_t)sOrig[r0 + i] * D + c0);
        o[0] = make_float4(v[0], v[1], v[2], v[3]);
        o[1] = make_float4(v[4], v[5], v[6], v[7]);
    }
}

// ======================= launch =======================
extern "C" void kernel_launch(void* const* d_in, const int* in_sizes, int n_in,
                              void* d_out, int out_size)
{
    const float* x      = (const float*)d_in[0];
    const float* Wg     = (const float*)d_in[1];
    const float* bg     = (const float*)d_in[2];
    const float* W_leaf = (const float*)d_in[3];
    const float* b_leaf = (const float*)d_in[4];
    const float* W_mid  = (const float*)d_in[5];
    const float* b_mid  = (const float*)d_in[6];
    const float* W_root = (const float*)d_in[7];
    const float* b_root = (const float*)d_in[8];
    float* out = (float*)d_out;

    cudaFuncSetAttribute(gate_kernel,
                         cudaFuncAttributeMaxDynamicSharedMemorySize, GATE_BYTES);
    cudaFuncSetAttribute(tree_mma_kernel,
                         cudaFuncAttributeMaxDynamicSharedMemorySize, MMA_SMEM);
    cudaFuncSetAttribute(fallback_kernel,
                         cudaFuncAttributeMaxDynamicSharedMemorySize, FB_BYTES);

    init_kernel<<<1, 32>>>();
    prep_w_kernel<<<7 * 65536 / 256, 256>>>(W_leaf, W_mid, W_root);
    gate_kernel<<<NB / GTILE, 256, GATE_BYTES>>>(x, Wg, bg);
    scan_kernel<<<1, 1>>>();
    scatter_kernel<<<NB / 256, 256>>>();
    tree_mma_kernel<<<NB / 128, 512, MMA_SMEM>>>(x, b_leaf, b_mid, b_root, out);
    fallback_kernel<<<NB / FTILE, 256, FB_BYTES>>>(
        x, W_leaf, b_leaf, W_mid, b_mid, W_root, b_root, out);
}